// round 15
// baseline (speedup 1.0000x reference)
#include <cuda_runtime.h>
#include <cuda_fp16.h>
#include <math.h>
#include <stdint.h>

// ---------------- problem constants ----------------
#define BSZ     8
#define SENC    3072
#define PRED    1024
#define ENCIN   40
#define DMODEL  128
#define NHEADS  4
#define DHEAD   32
#define NHASH   4
#define NBUCK   64
#define BUCKETSZ 64
#define NLAYERS 2
#define DFF     512
#define COUT    4
#define NCLASS  3
#define MARK    4
#define TLEN    4096
#define BHN     (BSZ*NHEADS)          // 32
#define MROWS   (BSZ*TLEN)            // 32768
#define NCHUNK  (NHASH*TLEN/BUCKETSZ) // 256
#define ITEMS   (NHASH*TLEN)          // 16384 per bh
#define ATTN_SCALE 0.17677669529663689f
#define HCHUNKS 16

// ---------------- scratch ----------------
__device__ float g_h[MROWS*DMODEL];
__device__ float g_res[MROWS*DMODEL];
__device__ float g_ff[MROWS*DFF];
__device__ float g_qk[BHN*TLEN*DHEAD];
__device__ float g_v[BHN*TLEN*DHEAD];
__device__ __half g_so16[(long)BHN*ITEMS*DHEAD];   // (bh, h, t, d)
__device__ float g_lse[BHN*ITEMS];                  // (bh, h, t)
__device__ int   g_st[BHN*ITEMS];
__device__ unsigned char g_bkt[BHN*ITEMS];
__device__ int   g_base[BHN*256];
__device__ float g_part[BSZ*HCHUNKS*3];

// ---------------- tf32 helpers ----------------
__device__ __forceinline__ uint32_t f2tf(float x) {
  uint32_t u; asm("cvt.rna.tf32.f32 %0, %1;" : "=r"(u) : "f"(x)); return u;
}
__device__ __forceinline__ void split_tf(float x, uint32_t& hi, uint32_t& lo) {
  hi = f2tf(x);
  lo = f2tf(x - __uint_as_float(hi));
}
__device__ __forceinline__ void mma_tf32(float* c, const uint32_t* a, const uint32_t* b) {
  asm volatile(
    "mma.sync.aligned.m16n8k8.row.col.f32.tf32.tf32.f32 "
    "{%0,%1,%2,%3}, {%4,%5,%6,%7}, {%8,%9}, {%0,%1,%2,%3};\n"
    : "+f"(c[0]), "+f"(c[1]), "+f"(c[2]), "+f"(c[3])
    : "r"(a[0]), "r"(a[1]), "r"(a[2]), "r"(a[3]), "r"(b[0]), "r"(b[1]));
}

// ---------------- fast exp on FMA/ALU pipes ----------------
__device__ __forceinline__ float exp_fast(float x) {
  float z = fmaxf(x * 1.4426950408889634f, -126.f);
  float t = z + 12582912.f;
  int   i = __float_as_int(t) - 0x4B400000;
  float f = z - (t - 12582912.f);
  float p = 1.3333558146e-3f;
  p = fmaf(p, f, 9.6181291076e-3f);
  p = fmaf(p, f, 5.5504108665e-2f);
  p = fmaf(p, f, 2.4022650696e-1f);
  p = fmaf(p, f, 6.9314718056e-1f);
  p = fmaf(p, f, 1.0f);
  return __int_as_float(__float_as_int(p) + (i << 23));
}

// ---------------- embedding (2 rows per 256-thread CTA) ----------------
__global__ void __launch_bounds__(256) embed_kernel(
    const float* __restrict__ xe, const float* __restrict__ xme,
    const float* __restrict__ xd, const float* __restrict__ xmd,
    const float* __restrict__ convw, const float* __restrict__ tw) {
  int rsel = threadIdx.x >> 7;             // 0/1: which row
  int d = threadIdx.x & 127;
  int bt = blockIdx.x * 2 + rsel;
  int b = bt / TLEN; int t = bt % TLEN;
  __shared__ float sx[2][3][ENCIN];
  __shared__ float sm[2][MARK];
  for (int i = d; i < 3*ENCIN; i += 128) {
    int k = i / ENCIN, c = i % ENCIN;
    int tt = t - 1 + k; tt = (tt + TLEN) % TLEN;
    float v = (tt < SENC) ? xe[(b*SENC + tt)*ENCIN + c]
                          : xd[(b*PRED + (tt - SENC))*ENCIN + c];
    sx[rsel][k][c] = v;
  }
  if (d < MARK)
    sm[rsel][d] = (t < SENC) ? xme[(b*SENC + t)*MARK + d]
                             : xmd[(b*PRED + (t - SENC))*MARK + d];
  __syncthreads();
  float acc = 0.f;
  #pragma unroll
  for (int k = 0; k < 3; k++)
    #pragma unroll
    for (int c = 0; c < ENCIN; c++)
      acc += sx[rsel][k][c] * convw[(k*ENCIN + c)*DMODEL + d];
  #pragma unroll
  for (int m = 0; m < MARK; m++) acc += sm[rsel][m] * tw[m*DMODEL + d];
  int i2 = (d >> 1) * 2;
  float div = expf((float)i2 * (-logf(10000.f) / (float)DMODEL));
  float ang = (float)t * div;
  acc += (d & 1) ? cosf(ang) : sinf(ang);
  g_h[(long)bt*DMODEL + d] = acc;
}

#define AS_STRIDE 20
#define BS_STRIDE 136

// ---------------- error-corrected TF32x3 GEMM (qk projection) ----------------
#define QK_SMEM_WORDS 18944
__global__ void __launch_bounds__(256, 2) gemm_qk_tf32x3(
    const float* __restrict__ A, const float* __restrict__ B,
    float* __restrict__ C, int M, int N, int K) {
  extern __shared__ __align__(16) uint32_t qsm[];
  uint32_t* Ash = qsm;
  uint32_t* Asl = qsm + 5120;
  uint32_t* Bsh = qsm + 10240;
  uint32_t* Bsl = qsm + 14592;
  #define ASH(b,r,c) Ash[(b)*2560 + (r)*AS_STRIDE + (c)]
  #define ASL(b,r,c) Asl[(b)*2560 + (r)*AS_STRIDE + (c)]
  #define BSH(b,r,c) Bsh[(b)*2176 + (r)*BS_STRIDE + (c)]
  #define BSL(b,r,c) Bsl[(b)*2176 + (r)*BS_STRIDE + (c)]
  int tid = threadIdx.x;
  int warp = tid >> 5, lane = tid & 31;
  int wm = warp >> 2, wn = warp & 3;
  int m_warp = wm * 64, n_warp = wn * 32;
  int g = lane >> 2, l4 = lane & 3;
  int bm = blockIdx.y * 128, bn = blockIdx.x * 128;

  int ar = tid >> 1, ac = (tid & 1) * 8;
  int bk = tid >> 5, bnn = (tid & 31) * 4;
  const float* Ap = A + (long)(bm + ar) * K + ac;
  const float* Bp = B + (long)bk * N + bn + bnn;

  float acc[4][4][4] = {};
  int ntiles = K >> 4;
  float4 fa0, fa1, fb0, fb1;
  fa0 = *(const float4*)(Ap);
  fa1 = *(const float4*)(Ap + 4);
  fb0 = *(const float4*)(Bp);
  fb1 = *(const float4*)(Bp + 8 * (long)N);
  int buf = 0;
  for (int t = 0; t < ntiles; t++) {
    float av[8] = {fa0.x,fa0.y,fa0.z,fa0.w,fa1.x,fa1.y,fa1.z,fa1.w};
    #pragma unroll
    for (int i = 0; i < 8; i++) {
      uint32_t hi, lo; split_tf(av[i], hi, lo);
      ASH(buf, ar, ac+i) = hi; ASL(buf, ar, ac+i) = lo;
    }
    float bv0[4] = {fb0.x,fb0.y,fb0.z,fb0.w};
    float bv1[4] = {fb1.x,fb1.y,fb1.z,fb1.w};
    #pragma unroll
    for (int i = 0; i < 4; i++) {
      uint32_t hi, lo; split_tf(bv0[i], hi, lo);
      BSH(buf, bk, bnn+i) = hi; BSL(buf, bk, bnn+i) = lo;
      split_tf(bv1[i], hi, lo);
      BSH(buf, bk+8, bnn+i) = hi; BSL(buf, bk+8, bnn+i) = lo;
    }
    __syncthreads();
    if (t + 1 < ntiles) {
      fa0 = *(const float4*)(Ap + (t+1)*16);
      fa1 = *(const float4*)(Ap + (t+1)*16 + 4);
      fb0 = *(const float4*)(Bp + (long)((t+1)*16) * N);
      fb1 = *(const float4*)(Bp + (long)((t+1)*16 + 8) * N);
    }
    #pragma unroll
    for (int k8 = 0; k8 < 16; k8 += 8) {
      uint32_t ah[4][4], al[4][4], bh[4][2], bl[4][2];
      #pragma unroll
      for (int mf = 0; mf < 4; mf++) {
        int mr = m_warp + mf*16 + g;
        ah[mf][0] = ASH(buf, mr    , k8 + l4);
        ah[mf][1] = ASH(buf, mr + 8, k8 + l4);
        ah[mf][2] = ASH(buf, mr    , k8 + l4 + 4);
        ah[mf][3] = ASH(buf, mr + 8, k8 + l4 + 4);
        al[mf][0] = ASL(buf, mr    , k8 + l4);
        al[mf][1] = ASL(buf, mr + 8, k8 + l4);
        al[mf][2] = ASL(buf, mr    , k8 + l4 + 4);
        al[mf][3] = ASL(buf, mr + 8, k8 + l4 + 4);
      }
      #pragma unroll
      for (int nf = 0; nf < 4; nf++) {
        int nc = n_warp + nf*8 + g;
        bh[nf][0] = BSH(buf, k8 + l4    , nc);
        bh[nf][1] = BSH(buf, k8 + l4 + 4, nc);
        bl[nf][0] = BSL(buf, k8 + l4    , nc);
        bl[nf][1] = BSL(buf, k8 + l4 + 4, nc);
      }
      #pragma unroll
      for (int mf = 0; mf < 4; mf++)
        #pragma unroll
        for (int nf = 0; nf < 4; nf++) {
          mma_tf32(acc[mf][nf], al[mf], bh[nf]);
          mma_tf32(acc[mf][nf], ah[mf], bl[nf]);
          mma_tf32(acc[mf][nf], ah[mf], bh[nf]);
        }
    }
    buf ^= 1;
  }
  #pragma unroll
  for (int mf = 0; mf < 4; mf++) {
    #pragma unroll
    for (int hf = 0; hf < 2; hf++) {
      int r = bm + m_warp + mf*16 + g + hf*8;
      #pragma unroll
      for (int nf = 0; nf < 4; nf++) {
        int c = bn + n_warp + nf*8 + 2*l4;
        float vx = acc[mf][nf][hf*2+0];
        float vy = acc[mf][nf][hf*2+1];
        int b = r / TLEN, t = r % TLEN;
        int hd = c >> 5, dh = c & 31;
        *(float2*)&C[(((long)b*NHEADS + hd)*TLEN + t)*DHEAD + dh] = make_float2(vx, vy);
      }
    }
  }
  #undef ASH
  #undef ASL
  #undef BSH
  #undef BSL
}

// ---------------- TF32 tensor-core GEMM 128x128 ----------------
// EPI: 0 none, 1 = +bias +residual +LayerNorm, 3 = +bias +GELU
template<int EPI, int SPLIT>
__global__ void __launch_bounds__(256, 2) gemm_tf32(
    const float* __restrict__ A, const float* __restrict__ B,
    const float* __restrict__ bias, const float* __restrict__ R,
    const float* __restrict__ lng, const float* __restrict__ lnb,
    float* __restrict__ C, int M, int N, int K) {
  __shared__ uint32_t As[2][128][AS_STRIDE];
  __shared__ uint32_t Bs[2][16][BS_STRIDE];
  int tid = threadIdx.x;
  int warp = tid >> 5, lane = tid & 31;
  int wm = warp >> 2, wn = warp & 3;
  int m_warp = wm * 64, n_warp = wn * 32;
  int g = lane >> 2, l4 = lane & 3;
  int bm = blockIdx.y * 128, bn = blockIdx.x * 128;

  int ar = tid >> 1, ac = (tid & 1) * 8;
  int bk = tid >> 5, bnn = (tid & 31) * 4;
  const float* Ap = A + (long)(bm + ar) * K + ac;
  const float* Bp = B + (long)bk * N + bn + bnn;

  float acc[4][4][4] = {};
  int ntiles = K >> 4;
  float4 fa0, fa1, fb0, fb1;
  fa0 = *(const float4*)(Ap);
  fa1 = *(const float4*)(Ap + 4);
  fb0 = *(const float4*)(Bp);
  fb1 = *(const float4*)(Bp + 8 * (long)N);
  int buf = 0;
  for (int t = 0; t < ntiles; t++) {
    As[buf][ar][ac+0] = f2tf(fa0.x); As[buf][ar][ac+1] = f2tf(fa0.y);
    As[buf][ar][ac+2] = f2tf(fa0.z); As[buf][ar][ac+3] = f2tf(fa0.w);
    As[buf][ar][ac+4] = f2tf(fa1.x); As[buf][ar][ac+5] = f2tf(fa1.y);
    As[buf][ar][ac+6] = f2tf(fa1.z); As[buf][ar][ac+7] = f2tf(fa1.w);
    Bs[buf][bk][bnn+0] = f2tf(fb0.x); Bs[buf][bk][bnn+1] = f2tf(fb0.y);
    Bs[buf][bk][bnn+2] = f2tf(fb0.z); Bs[buf][bk][bnn+3] = f2tf(fb0.w);
    Bs[buf][bk+8][bnn+0] = f2tf(fb1.x); Bs[buf][bk+8][bnn+1] = f2tf(fb1.y);
    Bs[buf][bk+8][bnn+2] = f2tf(fb1.z); Bs[buf][bk+8][bnn+3] = f2tf(fb1.w);
    __syncthreads();
    if (t + 1 < ntiles) {
      fa0 = *(const float4*)(Ap + (t+1)*16);
      fa1 = *(const float4*)(Ap + (t+1)*16 + 4);
      fb0 = *(const float4*)(Bp + (long)((t+1)*16) * N);
      fb1 = *(const float4*)(Bp + (long)((t+1)*16 + 8) * N);
    }
    #pragma unroll
    for (int k8 = 0; k8 < 16; k8 += 8) {
      uint32_t afr[4][4], bfr[4][2];
      #pragma unroll
      for (int mf = 0; mf < 4; mf++) {
        int mr = m_warp + mf*16 + g;
        afr[mf][0] = As[buf][mr    ][k8 + l4];
        afr[mf][1] = As[buf][mr + 8][k8 + l4];
        afr[mf][2] = As[buf][mr    ][k8 + l4 + 4];
        afr[mf][3] = As[buf][mr + 8][k8 + l4 + 4];
      }
      #pragma unroll
      for (int nf = 0; nf < 4; nf++) {
        int nc = n_warp + nf*8 + g;
        bfr[nf][0] = Bs[buf][k8 + l4    ][nc];
        bfr[nf][1] = Bs[buf][k8 + l4 + 4][nc];
      }
      #pragma unroll
      for (int mf = 0; mf < 4; mf++)
        #pragma unroll
        for (int nf = 0; nf < 4; nf++)
          mma_tf32(acc[mf][nf], afr[mf], bfr[nf]);
    }
    buf ^= 1;
  }

  if (EPI == 1) {
    float* Ssum = (float*)As;
    float* Ssq  = ((float*)As) + 512;
    __syncthreads();
    float psum[4][2], psq[4][2];
    #pragma unroll
    for (int mf = 0; mf < 4; mf++) {
      #pragma unroll
      for (int hf = 0; hf < 2; hf++) {
        int r = bm + m_warp + mf*16 + g + hf*8;
        float s = 0.f, sq = 0.f;
        #pragma unroll
        for (int nf = 0; nf < 4; nf++) {
          int c = n_warp + nf*8 + 2*l4;
          #pragma unroll
          for (int p = 0; p < 2; p++) {
            float v = acc[mf][nf][hf*2+p] + bias[c+p] + R[(long)r*N + c + p];
            acc[mf][nf][hf*2+p] = v;
            s += v; sq += v*v;
          }
        }
        s  += __shfl_xor_sync(0xffffffffu, s, 1);
        s  += __shfl_xor_sync(0xffffffffu, s, 2);
        sq += __shfl_xor_sync(0xffffffffu, sq, 1);
        sq += __shfl_xor_sync(0xffffffffu, sq, 2);
        psum[mf][hf] = s; psq[mf][hf] = sq;
      }
    }
    if (l4 == 0) {
      #pragma unroll
      for (int mf = 0; mf < 4; mf++)
        #pragma unroll
        for (int hf = 0; hf < 2; hf++) {
          int rl = m_warp + mf*16 + g + hf*8;
          Ssum[rl*4 + wn] = psum[mf][hf];
          Ssq [rl*4 + wn] = psq[mf][hf];
        }
    }
    __syncthreads();
    #pragma unroll
    for (int mf = 0; mf < 4; mf++) {
      #pragma unroll
      for (int hf = 0; hf < 2; hf++) {
        int rl = m_warp + mf*16 + g + hf*8;
        int r = bm + rl;
        float s  = Ssum[rl*4+0] + Ssum[rl*4+1] + Ssum[rl*4+2] + Ssum[rl*4+3];
        float sq = Ssq [rl*4+0] + Ssq [rl*4+1] + Ssq [rl*4+2] + Ssq [rl*4+3];
        float mean = s * (1.f/128.f);
        float var = sq * (1.f/128.f) - mean*mean;
        float rstd = rsqrtf(var + 1e-5f);
        #pragma unroll
        for (int nf = 0; nf < 4; nf++) {
          int c = n_warp + nf*8 + 2*l4;
          float2 o;
          o.x = (acc[mf][nf][hf*2+0] - mean)*rstd*lng[c+0] + lnb[c+0];
          o.y = (acc[mf][nf][hf*2+1] - mean)*rstd*lng[c+1] + lnb[c+1];
          *(float2*)&C[(long)r*N + c] = o;
        }
      }
    }
  } else {
    #pragma unroll
    for (int mf = 0; mf < 4; mf++) {
      #pragma unroll
      for (int hf = 0; hf < 2; hf++) {
        int r = bm + m_warp + mf*16 + g + hf*8;
        #pragma unroll
        for (int nf = 0; nf < 4; nf++) {
          int c = bn + n_warp + nf*8 + 2*l4;
          float vx = acc[mf][nf][hf*2+0];
          float vy = acc[mf][nf][hf*2+1];
          if (EPI == 3) {
            vx += bias[c+0]; vy += bias[c+1];
            vx = 0.5f*vx*(1.f + erff(vx*0.70710678118f));
            vy = 0.5f*vy*(1.f + erff(vy*0.70710678118f));
          }
          if (SPLIT) {
            int b = r / TLEN, t = r % TLEN;
            int hd = c >> 5, dh = c & 31;
            *(float2*)&C[(((long)b*NHEADS + hd)*TLEN + t)*DHEAD + dh] = make_float2(vx, vy);
          } else {
            *(float2*)&C[(long)r*N + c] = make_float2(vx, vy);
          }
        }
      }
    }
  }
}

// ---------------- Wo GEMM with fused cross-hash combine ----------------
__global__ void __launch_bounds__(256, 2) gemm_wo_fused(
    const float* __restrict__ B,
    const float* __restrict__ bias, const float* __restrict__ R,
    const float* __restrict__ lng, const float* __restrict__ lnb,
    float* __restrict__ C, int M, int N, int K) {
  __shared__ uint32_t As[2][128][AS_STRIDE];
  __shared__ uint32_t Bs[2][16][BS_STRIDE];
  int tid = threadIdx.x;
  int warp = tid >> 5, lane = tid & 31;
  int wm = warp >> 2, wn = warp & 3;
  int m_warp = wm * 64, n_warp = wn * 32;
  int g = lane >> 2, l4 = lane & 3;
  int bm = blockIdx.y * 128;

  int ar = tid >> 1, ac = (tid & 1) * 8;
  int bk = tid >> 5, bnn = (tid & 31) * 4;
  int arow = bm + ar;
  int bq = arow >> 12, tq = arow & (TLEN - 1);
  const float* Bp = B + (long)bk * N + bnn;

  float acc[4][4][4] = {};
  int ntiles = K >> 4;   // 8
  float4 fb0, fb1;
  fb0 = *(const float4*)(Bp);
  fb1 = *(const float4*)(Bp + 8 * (long)N);
  int buf = 0;
  for (int t = 0; t < ntiles; t++) {
    {
      int k0 = t*16 + ac;
      int head = k0 >> 5, dh = k0 & 31;
      long rowbase = (long)((bq*NHEADS + head)*NHASH)*TLEN + tq;
      const float* lsep = g_lse + rowbase;
      float l0 = lsep[0], l1 = lsep[TLEN], l2 = lsep[2*TLEN], l3 = lsep[3*TLEN];
      float mm = fmaxf(fmaxf(l0, l1), fmaxf(l2, l3));
      float w0 = exp_fast(l0 - mm), w1 = exp_fast(l1 - mm);
      float w2 = exp_fast(l2 - mm), w3 = exp_fast(l3 - mm);
      float invw = 1.f / (w0 + w1 + w2 + w3);
      w0 *= invw; w1 *= invw; w2 *= invw; w3 *= invw;
      const __half* sop = g_so16 + rowbase*DHEAD + dh;
      uint4 u0 = *(const uint4*)(sop);
      uint4 u1 = *(const uint4*)(sop + (long)TLEN*DHEAD);
      uint4 u2 = *(const uint4*)(sop + 2L*TLEN*DHEAD);
      uint4 u3 = *(const uint4*)(sop + 3L*TLEN*DHEAD);
      const __half2* p0 = (const __half2*)&u0;
      const __half2* p1 = (const __half2*)&u1;
      const __half2* p2 = (const __half2*)&u2;
      const __half2* p3 = (const __half2*)&u3;
      #pragma unroll
      for (int i = 0; i < 4; i++) {
        float2 a0 = __half22float2(p0[i]);
        float2 a1 = __half22float2(p1[i]);
        float2 a2 = __half22float2(p2[i]);
        float2 a3 = __half22float2(p3[i]);
        float vx = w0*a0.x + w1*a1.x + w2*a2.x + w3*a3.x;
        float vy = w0*a0.y + w1*a1.y + w2*a2.y + w3*a3.y;
        As[buf][ar][ac + 2*i    ] = f2tf(vx);
        As[buf][ar][ac + 2*i + 1] = f2tf(vy);
      }
    }
    Bs[buf][bk][bnn+0] = f2tf(fb0.x); Bs[buf][bk][bnn+1] = f2tf(fb0.y);
    Bs[buf][bk][bnn+2] = f2tf(fb0.z); Bs[buf][bk][bnn+3] = f2tf(fb0.w);
    Bs[buf][bk+8][bnn+0] = f2tf(fb1.x); Bs[buf][bk+8][bnn+1] = f2tf(fb1.y);
    Bs[buf][bk+8][bnn+2] = f2tf(fb1.z); Bs[buf][bk+8][bnn+3] = f2tf(fb1.w);
    __syncthreads();
    if (t + 1 < ntiles) {
      fb0 = *(const float4*)(Bp + (long)((t+1)*16) * N);
      fb1 = *(const float4*)(Bp + (long)((t+1)*16 + 8) * N);
    }
    #pragma unroll
    for (int k8 = 0; k8 < 16; k8 += 8) {
      uint32_t afr[4][4], bfr[4][2];
      #pragma unroll
      for (int mf = 0; mf < 4; mf++) {
        int mr = m_warp + mf*16 + g;
        afr[mf][0] = As[buf][mr    ][k8 + l4];
        afr[mf][1] = As[buf][mr + 8][k8 + l4];
        afr[mf][2] = As[buf][mr    ][k8 + l4 + 4];
        afr[mf][3] = As[buf][mr + 8][k8 + l4 + 4];
      }
      #pragma unroll
      for (int nf = 0; nf < 4; nf++) {
        int nc = n_warp + nf*8 + g;
        bfr[nf][0] = Bs[buf][k8 + l4    ][nc];
        bfr[nf][1] = Bs[buf][k8 + l4 + 4][nc];
      }
      #pragma unroll
      for (int mf = 0; mf < 4; mf++)
        #pragma unroll
        for (int nf = 0; nf < 4; nf++)
          mma_tf32(acc[mf][nf], afr[mf], bfr[nf]);
    }
    buf ^= 1;
  }

  float* Ssum = (float*)As;
  float* Ssq  = ((float*)As) + 512;
  __syncthreads();
  float psum[4][2], psq[4][2];
  #pragma unroll
  for (int mf = 0; mf < 4; mf++) {
    #pragma unroll
    for (int hf = 0; hf < 2; hf++) {
      int r = bm + m_warp + mf*16 + g + hf*8;
      float s = 0.f, sq = 0.f;
      #pragma unroll
      for (int nf = 0; nf < 4; nf++) {
        int c = n_warp + nf*8 + 2*l4;
        #pragma unroll
        for (int p = 0; p < 2; p++) {
          float v = acc[mf][nf][hf*2+p] + bias[c+p] + R[(long)r*N + c + p];
          acc[mf][nf][hf*2+p] = v;
          s += v; sq += v*v;
        }
      }
      s  += __shfl_xor_sync(0xffffffffu, s, 1);
      s  += __shfl_xor_sync(0xffffffffu, s, 2);
      sq += __shfl_xor_sync(0xffffffffu, sq, 1);
      sq += __shfl_xor_sync(0xffffffffu, sq, 2);
      psum[mf][hf] = s; psq[mf][hf] = sq;
    }
  }
  if (l4 == 0) {
    #pragma unroll
    for (int mf = 0; mf < 4; mf++)
      #pragma unroll
      for (int hf = 0; hf < 2; hf++) {
        int rl = m_warp + mf*16 + g + hf*8;
        Ssum[rl*4 + wn] = psum[mf][hf];
        Ssq [rl*4 + wn] = psq[mf][hf];
      }
  }
  __syncthreads();
  #pragma unroll
  for (int mf = 0; mf < 4; mf++) {
    #pragma unroll
    for (int hf = 0; hf < 2; hf++) {
      int rl = m_warp + mf*16 + g + hf*8;
      int r = bm + rl;
      float s  = Ssum[rl*4+0] + Ssum[rl*4+1] + Ssum[rl*4+2] + Ssum[rl*4+3];
      float sq = Ssq [rl*4+0] + Ssq [rl*4+1] + Ssq [rl*4+2] + Ssq [rl*4+3];
      float mean = s * (1.f/128.f);
      float var = sq * (1.f/128.f) - mean*mean;
      float rstd = rsqrtf(var + 1e-5f);
      #pragma unroll
      for (int nf = 0; nf < 4; nf++) {
        int c = n_warp + nf*8 + 2*l4;
        float2 o;
        o.x = (acc[mf][nf][hf*2+0] - mean)*rstd*lng[c+0] + lnb[c+0];
        o.y = (acc[mf][nf][hf*2+1] - mean)*rstd*lng[c+1] + lnb[c+1];
        *(float2*)&C[(long)r*N + c] = o;
      }
    }
  }
}

// ---------------- fused rotation + argmax (256 thr, 128 rows/CTA) ----------------
#define ROT_ROWS 128
__global__ void __launch_bounds__(256) rot_argmax_kernel(const float* __restrict__ rot_l) {
  __shared__ __align__(16) float qT[32][ROT_ROWS + 4];   // [d][row]
  int tid = threadIdx.x, lane = tid & 31;
  int col = tid & 127;                 // rotation column (h*32 + bucket-lane)
  int h = (tid >> 5) & 3;              // hash of this warp
  int half = tid >> 7;                 // row-group 0/1 (rows half*64 .. +63)
  long row0 = (long)blockIdx.x * ROT_ROWS;
  int bh = (int)(row0 >> 12);
  int t0 = (int)(row0 & (TLEN - 1));

  float rcol[32];
  #pragma unroll
  for (int d = 0; d < 32; d++) rcol[d] = rot_l[d*128 + col];

  {
    int r = tid >> 1;                  // 0..127 rows
    int halfd = (tid & 1) * 16;
    const float* gq = g_qk + (row0 + r)*DHEAD + halfd;
    #pragma unroll
    for (int f = 0; f < 4; f++) {
      float4 v = *(const float4*)(gq + f*4);
      qT[halfd + f*4 + 0][r] = v.x; qT[halfd + f*4 + 1][r] = v.y;
      qT[halfd + f*4 + 2][r] = v.z; qT[halfd + f*4 + 3][r] = v.w;
    }
  }
  __syncthreads();

  unsigned char* bp = g_bkt + (bh*NHASH + h)*TLEN + t0 + half*64;
  #pragma unroll 4
  for (int rg = 0; rg < 16; rg++) {
    int rb = half*64 + rg*4;
    float a0 = 0.f, a1 = 0.f, a2 = 0.f, a3 = 0.f;
    #pragma unroll
    for (int d = 0; d < 32; d++) {
      float4 q4 = *(const float4*)&qT[d][rb];
      float r = rcol[d];
      a0 += q4.x * r; a1 += q4.y * r; a2 += q4.z * r; a3 += q4.w * r;
    }
    #pragma unroll
    for (int rr = 0; rr < 4; rr++) {
      float v = (rr == 0) ? a0 : (rr == 1) ? a1 : (rr == 2) ? a2 : a3;
      uint32_t key = __float_as_uint(fabsf(v));
      uint32_t mx = __reduce_max_sync(0xffffffffu, key);
      bool eq = (key == mx);
      bool pos = (v >= -v);
      unsigned bpos = __ballot_sync(0xffffffffu, eq && pos);
      unsigned bneg = __ballot_sync(0xffffffffu, eq && !pos);
      int bucket = bpos ? (__ffs(bpos) - 1) : (__ffs(bneg) + 31);
      if (lane == 0) bp[rg*4 + rr] = (unsigned char)bucket;
    }
  }
}

// ---------------- counting sort: histogram + scan ----------------
__global__ void hist_kernel() {
  __shared__ int cnt[256];
  int bh = blockIdx.x, tid = threadIdx.x;
  cnt[tid] = 0; __syncthreads();
  const unsigned char* bp = g_bkt + bh*ITEMS;
  for (int i = tid; i < ITEMS; i += 256) {
    int gb = ((i >> 12) << 6) + bp[i];
    atomicAdd(&cnt[gb], 1);
  }
  __syncthreads();
  if (tid == 0) {
    int s = 0;
    #pragma unroll 8
    for (int j = 0; j < 256; j++) { g_base[bh*256 + j] = s; s += cnt[j]; }
  }
}

__global__ void __launch_bounds__(1024) place_kernel() {
  int bhh = blockIdx.x;
  int bh = bhh >> 2, h = bhh & 3;
  int warp = threadIdx.x >> 5, lane = threadIdx.x & 31;
  const unsigned char* bp = g_bkt + (bh*NHASH + h)*TLEN;
  #pragma unroll
  for (int s = 0; s < 2; s++) {
    int lb = warp*2 + s;
    int base = g_base[bh*256 + h*64 + lb];
    for (int t0 = 0; t0 < TLEN; t0 += 32) {
      int my = bp[t0 + lane];
      unsigned mask = __ballot_sync(0xffffffffu, my == lb);
      if (my == lb) {
        int p = base + __popc(mask & ((1u << lane) - 1u));
        g_st[bh*ITEMS + p] = t0 + lane;
      }
      base += __popc(mask);
    }
  }
}

// ---------------- tensor-core LSH attention ----------------
#define ATTN_SMEM_WORDS 13760
__global__ void __launch_bounds__(128, 4) attn_kernel() {
  extern __shared__ __align__(16) uint32_t smw[];
  uint32_t* qS  = smw;
  uint32_t* kTd = smw + 2304;
  uint32_t* pS  = smw;
  uint32_t* vS  = smw + 8448;
  int* sQt = (int*)(smw + 13568);
  int* sKt = (int*)(smw + 13632);

  int bh = blockIdx.x >> 8;
  int c  = blockIdx.x & 255;
  int pc = (c + 255) & 255;
  int hh = c >> 6;
  int tid = threadIdx.x;
  int lane = tid & 31, warp = tid >> 5;
  int g = lane >> 2, l4 = lane & 3;

  {
    int p = (tid < 64) ? (c*64 + tid) : (pc*64 + (tid - 64));
    sKt[tid] = g_st[bh*ITEMS + p];
    if (tid < 64) sQt[tid] = sKt[tid];
  }
  __syncthreads();

  {
    int j = tid;
    int t = sKt[j];
    const float* gk = g_qk + ((long)bh*TLEN + t)*DHEAD;
    const float* gv = g_v  + ((long)bh*TLEN + t)*DHEAD;
    float4 kr[8];
    float ss = 0.f;
    #pragma unroll
    for (int f = 0; f < 8; f++) {
      kr[f] = *(const float4*)(gk + f*4);
      ss += kr[f].x*kr[f].x + kr[f].y*kr[f].y + kr[f].z*kr[f].z + kr[f].w*kr[f].w;
    }
    if (j < 64) {
      #pragma unroll
      for (int f = 0; f < 8; f++) {
        uint4 u;
        u.x = f2tf(kr[f].x); u.y = f2tf(kr[f].y); u.z = f2tf(kr[f].z); u.w = f2tf(kr[f].w);
        *(uint4*)&qS[j*36 + f*4] = u;
      }
    }
    float inv = ATTN_SCALE / fmaxf(sqrtf(ss), 1e-12f);
    #pragma unroll
    for (int f = 0; f < 8; f++) {
      kTd[(f*4+0)*136 + j] = f2tf(kr[f].x * inv);
      kTd[(f*4+1)*136 + j] = f2tf(kr[f].y * inv);
      kTd[(f*4+2)*136 + j] = f2tf(kr[f].z * inv);
      kTd[(f*4+3)*136 + j] = f2tf(kr[f].w * inv);
    }
    #pragma unroll
    for (int f = 0; f < 8; f++) {
      float4 vv = *(const float4*)(gv + f*4);
      uint4 u;
      u.x = f2tf(vv.x); u.y = f2tf(vv.y); u.z = f2tf(vv.z); u.w = f2tf(vv.w);
      *(uint4*)&vS[j*40 + f*4] = u;
    }
  }
  __syncthreads();

  int mb = warp * 16;
  float s[16][4];
  #pragma unroll
  for (int nt = 0; nt < 16; nt++)
    #pragma unroll
    for (int p = 0; p < 4; p++) s[nt][p] = 0.f;
  #pragma unroll
  for (int k8 = 0; k8 < 32; k8 += 8) {
    uint32_t afr[4];
    afr[0] = qS[(mb + g    )*36 + k8 + l4];
    afr[1] = qS[(mb + g + 8)*36 + k8 + l4];
    afr[2] = qS[(mb + g    )*36 + k8 + l4 + 4];
    afr[3] = qS[(mb + g + 8)*36 + k8 + l4 + 4];
    #pragma unroll
    for (int nt = 0; nt < 16; nt++) {
      uint32_t bfr[2];
      bfr[0] = kTd[(k8 + l4    )*136 + nt*8 + g];
      bfr[1] = kTd[(k8 + l4 + 4)*136 + nt*8 + g];
      mma_tf32(s[nt], afr, bfr);
    }
  }
  __syncthreads();

  int r0 = mb + g, r1 = mb + g + 8;
  int qt0 = sQt[r0], qt1 = sQt[r1];
  float m0 = -1e30f, m1 = -1e30f;
  #pragma unroll
  for (int nt = 0; nt < 16; nt++) {
    int j0 = nt*8 + 2*l4;
    int kt0 = sKt[j0], kt1 = sKt[j0+1];
    if (kt0 == qt0) s[nt][0] = -5e4f;
    if (kt1 == qt0) s[nt][1] = -5e4f;
    if (kt0 == qt1) s[nt][2] = -5e4f;
    if (kt1 == qt1) s[nt][3] = -5e4f;
    m0 = fmaxf(m0, fmaxf(s[nt][0], s[nt][1]));
    m1 = fmaxf(m1, fmaxf(s[nt][2], s[nt][3]));
  }
  m0 = fmaxf(m0, __shfl_xor_sync(0xffffffffu, m0, 1));
  m0 = fmaxf(m0, __shfl_xor_sync(0xffffffffu, m0, 2));
  m1 = fmaxf(m1, __shfl_xor_sync(0xffffffffu, m1, 1));
  m1 = fmaxf(m1, __shfl_xor_sync(0xffffffffu, m1, 2));
  float sum0 = 0.f, sum1 = 0.f;
  #pragma unroll
  for (int nt = 0; nt < 16; nt++) {
    int j0 = nt*8 + 2*l4;
    uint32_t e00 = f2tf(exp_fast(s[nt][0] - m0));
    uint32_t e01 = f2tf(exp_fast(s[nt][1] - m0));
    uint32_t e10 = f2tf(exp_fast(s[nt][2] - m1));
    uint32_t e11 = f2tf(exp_fast(s[nt][3] - m1));
    sum0 += __uint_as_float(e00) + __uint_as_float(e01);
    sum1 += __uint_as_float(e10) + __uint_as_float(e11);
    *(uint2*)&pS[r0*132 + j0] = make_uint2(e00, e01);
    *(uint2*)&pS[r1*132 + j0] = make_uint2(e10, e11);
  }
  sum0 += __shfl_xor_sync(0xffffffffu, sum0, 1);
  sum0 += __shfl_xor_sync(0xffffffffu, sum0, 2);
  sum1 += __shfl_xor_sync(0xffffffffu, sum1, 1);
  sum1 += __shfl_xor_sync(0xffffffffu, sum1, 2);
  long lbase = (long)(bh*NHASH + hh)*TLEN;
  if (l4 == 0) {
    g_lse[lbase + qt0] = m0 + __logf(sum0);
    g_lse[lbase + qt1] = m1 + __logf(sum1);
  }
  __syncwarp();

  float o[4][4];
  #pragma unroll
  for (int nt = 0; nt < 4; nt++)
    #pragma unroll
    for (int p = 0; p < 4; p++) o[nt][p] = 0.f;
  #pragma unroll
  for (int k8 = 0; k8 < 128; k8 += 8) {
    uint32_t afr[4];
    afr[0] = pS[(mb + g    )*132 + k8 + l4];
    afr[1] = pS[(mb + g + 8)*132 + k8 + l4];
    afr[2] = pS[(mb + g    )*132 + k8 + l4 + 4];
    afr[3] = pS[(mb + g + 8)*132 + k8 + l4 + 4];
    #pragma unroll
    for (int nt = 0; nt < 4; nt++) {
      uint32_t bfr[2];
      bfr[0] = vS[(k8 + l4    )*40 + nt*8 + g];
      bfr[1] = vS[(k8 + l4 + 4)*40 + nt*8 + g];
      mma_tf32(o[nt], afr, bfr);
    }
  }
  float inv0 = 1.f / sum0, inv1 = 1.f / sum1;
  __half* outp = g_so16 + lbase*DHEAD;
  #pragma unroll
  for (int nt = 0; nt < 4; nt++) {
    int d0 = nt*8 + 2*l4;
    *(__half2*)&outp[(long)qt0*DHEAD + d0] = __floats2half2_rn(o[nt][0]*inv0, o[nt][1]*inv0);
    *(__half2*)&outp[(long)qt1*DHEAD + d0] = __floats2half2_rn(o[nt][2]*inv1, o[nt][3]*inv1);
  }
}

// ---------------- final layernorm, tail rows only ----------------
__global__ void ln_tail_kernel(const float* __restrict__ in, float* __restrict__ out,
                               const float* __restrict__ g, const float* __restrict__ bb) {
  int idx = blockIdx.x;
  int b = idx >> 10, tt = idx & (PRED - 1);
  long row = (long)b*TLEN + SENC + tt;
  int d = threadIdx.x;
  __shared__ float red[4];
  float x = in[row*DMODEL + d];
  float s = x;
  #pragma unroll
  for (int off = 16; off; off >>= 1) s += __shfl_xor_sync(0xffffffffu, s, off);
  if ((d & 31) == 0) red[d >> 5] = s;
  __syncthreads();
  float mean = (red[0]+red[1]+red[2]+red[3]) * (1.f/DMODEL);
  float dv = x - mean;
  float s2 = dv*dv;
  #pragma unroll
  for (int off = 16; off; off >>= 1) s2 += __shfl_xor_sync(0xffffffffu, s2, off);
  __syncthreads();
  if ((d & 31) == 0) red[d >> 5] = s2;
  __syncthreads();
  float var = (red[0]+red[1]+red[2]+red[3]) * (1.f/DMODEL);
  out[row*DMODEL + d] = dv * rsqrtf(var + 1e-5f) * g[d] + bb[d];
}

// ---------------- head: parallel partial logits ----------------
__global__ void head_part_kernel(const float* __restrict__ projw, const float* __restrict__ projb,
                                 const float* __restrict__ fcw) {
  int b = blockIdx.x, chunk = blockIdx.y;
  int tid = threadIdx.x;
  int tt = chunk * 64 + tid;
  const float* hh = g_res + ((long)b*TLEN + SENC + tt)*DMODEL;
  float o4[4];
  #pragma unroll
  for (int cc = 0; cc < 4; cc++) {
    float a = projb[cc];
    #pragma unroll 8
    for (int d = 0; d < DMODEL; d++) a += hh[d]*projw[d*4 + cc];
    o4[cc] = a;
  }
  float lg0 = 0.f, lg1 = 0.f, lg2 = 0.f;
  #pragma unroll
  for (int cc = 0; cc < 4; cc++) {
    int idx = (tt*4 + cc)*3;
    lg0 += o4[cc]*fcw[idx+0];
    lg1 += o4[cc]*fcw[idx+1];
    lg2 += o4[cc]*fcw[idx+2];
  }
  __shared__ float red[3][64];
  red[0][tid] = lg0; red[1][tid] = lg1; red[2][tid] = lg2;
  __syncthreads();
  for (int off = 32; off; off >>= 1) {
    if (tid < off) {
      red[0][tid] += red[0][tid+off];
      red[1][tid] += red[1][tid+off];
      red[2][tid] += red[2][tid+off];
    }
    __syncthreads();
  }
  if (tid == 0) {
    g_part[(b*HCHUNKS + chunk)*3 + 0] = red[0][0];
    g_part[(b*HCHUNKS + chunk)*3 + 1] = red[1][0];
    g_part[(b*HCHUNKS + chunk)*3 + 2] = red[2][0];
  }
}

__global__ void head_finish_kernel(const float* __restrict__ fcb, float* __restrict__ dout) {
  int b = threadIdx.x;
  if (b >= BSZ) return;
  float l0 = fcb[0], l1 = fcb[1], l2 = fcb[2];
  for (int c = 0; c < HCHUNKS; c++) {
    l0 += g_part[(b*HCHUNKS + c)*3 + 0];
    l1 += g_part[(b*HCHUNKS + c)*3 + 1];
    l2 += g_part[(b*HCHUNKS + c)*3 + 2];
  }
  float mx = fmaxf(l0, fmaxf(l1, l2));
  float e0 = expf(l0-mx), e1 = expf(l1-mx), e2 = expf(l2-mx);
  float is = 1.f/(e0+e1+e2);
  dout[b*3+0] = e0*is; dout[b*3+1] = e1*is; dout[b*3+2] = e2*is;
}

// ---------------- host launch ----------------
extern "C" void kernel_launch(void* const* d_in, const int* in_sizes, int n_in,
                              void* d_out, int out_size) {
  const float* x_enc      = (const float*)d_in[0];
  const float* x_mark_enc = (const float*)d_in[1];
  const float* x_dec      = (const float*)d_in[2];
  const float* x_mark_dec = (const float*)d_in[3];
  const float* conv_w     = (const float*)d_in[4];
  const float* timef_w    = (const float*)d_in[5];
  const float* Wqk        = (const float*)d_in[6];
  const float* Wv         = (const float*)d_in[7];
  const float* Wo         = (const float*)d_in[8];
  const float* bo         = (const float*)d_in[9];
  const float* rot        = (const float*)d_in[10];
  const float* ln1_g      = (const float*)d_in[11];
  const float* ln1_b      = (const float*)d_in[12];
  const float* ln2_g      = (const float*)d_in[13];
  const float* ln2_b      = (const float*)d_in[14];
  const float* w1         = (const float*)d_in[15];
  const float* b1         = (const float*)d_in[16];
  const float* w2         = (const float*)d_in[17];
  const float* b2         = (const float*)d_in[18];
  const float* lnf_g      = (const float*)d_in[19];
  const float* lnf_b      = (const float*)d_in[20];
  const float* proj_w     = (const float*)d_in[21];
  const float* proj_b     = (const float*)d_in[22];
  const float* fc1_w      = (const float*)d_in[23];
  const float* fc1_b      = (const float*)d_in[24];
  (void)in_sizes; (void)n_in; (void)out_size;

  void* p;
  cudaGetSymbolAddress(&p, g_h);    float* ph    = (float*)p;
  cudaGetSymbolAddress(&p, g_res);  float* pres  = (float*)p;
  cudaGetSymbolAddress(&p, g_ff);   float* pff   = (float*)p;
  cudaGetSymbolAddress(&p, g_qk);   float* pqk   = (float*)p;
  cudaGetSymbolAddress(&p, g_v);    float* pv    = (float*)p;

  const int attn_smem = ATTN_SMEM_WORDS * 4;
  cudaFuncSetAttribute(attn_kernel, cudaFuncAttributeMaxDynamicSharedMemorySize, attn_smem);
  const int qk_smem = QK_SMEM_WORDS * 4;
  cudaFuncSetAttribute(gemm_qk_tf32x3, cudaFuncAttributeMaxDynamicSharedMemorySize, qk_smem);

  embed_kernel<<<MROWS/2, 256>>>(x_enc, x_mark_enc, x_dec, x_mark_dec, conv_w, timef_w);

  for (int l = 0; l < NLAYERS; l++) {
    const float* Wqk_l = Wqk + (long)l*DMODEL*DMODEL;
    const float* Wv_l  = Wv  + (long)l*DMODEL*DMODEL;
    const float* Wo_l  = Wo  + (long)l*DMODEL*DMODEL;
    const float* bo_l  = bo  + l*DMODEL;
    const float* rot_l = rot + (long)l*DHEAD*NHASH*(NBUCK/2);
    const float* w1_l  = w1 + (long)l*DMODEL*DFF;
    const float* b1_l  = b1 + l*DFF;
    const float* w2_l  = w2 + (long)l*DFF*DMODEL;
    const float* b2_l  = b2 + l*DMODEL;

    gemm_qk_tf32x3<<<dim3(1,256), 256, qk_smem>>>(ph, Wqk_l, pqk, MROWS, DMODEL, DMODEL);
    gemm_tf32<0,1><<<dim3(1,256), 256>>>(ph, Wv_l, nullptr, nullptr, nullptr, nullptr, pv, MROWS, DMODEL, DMODEL);

    rot_argmax_kernel<<<BHN*TLEN/ROT_ROWS, 256>>>(rot_l);

    hist_kernel<<<BHN, 256>>>();
    place_kernel<<<BHN*NHASH, 1024>>>();

    attn_kernel<<<BHN*NCHUNK, 128, attn_smem>>>();

    gemm_wo_fused<<<dim3(1,256), 256>>>(Wo_l, bo_l, ph, ln1_g + l*DMODEL, ln1_b + l*DMODEL,
                                        ph, MROWS, DMODEL, DMODEL);
    gemm_tf32<3,0><<<dim3(4,256), 256>>>(ph, w1_l, b1_l, nullptr, nullptr, nullptr, pff, MROWS, DFF, DMODEL);
    gemm_tf32<1,0><<<dim3(1,256), 256>>>(pff, w2_l, b2_l, ph, ln2_g + l*DMODEL, ln2_b + l*DMODEL,
                                         ph, MROWS, DMODEL, DFF);
  }

  ln_tail_kernel<<<BSZ*PRED, 128>>>(ph, pres, lnf_g, lnf_b);
  head_part_kernel<<<dim3(BSZ, HCHUNKS), 64>>>(proj_w, proj_b, fc1_w);
  head_finish_kernel<<<1, 32>>>(fc1_b, (float*)d_out);
}

// round 16
// speedup vs baseline: 1.0626x; 1.0626x over previous
#include <cuda_runtime.h>
#include <cuda_fp16.h>
#include <math.h>
#include <stdint.h>

// ---------------- problem constants ----------------
#define BSZ     8
#define SENC    3072
#define PRED    1024
#define ENCIN   40
#define DMODEL  128
#define NHEADS  4
#define DHEAD   32
#define NHASH   4
#define NBUCK   64
#define BUCKETSZ 64
#define NLAYERS 2
#define DFF     512
#define COUT    4
#define NCLASS  3
#define MARK    4
#define TLEN    4096
#define BHN     (BSZ*NHEADS)          // 32
#define MROWS   (BSZ*TLEN)            // 32768
#define NCHUNK  (NHASH*TLEN/BUCKETSZ) // 256
#define ITEMS   (NHASH*TLEN)          // 16384 per bh
#define ATTN_SCALE 0.17677669529663689f
#define HCHUNKS 16

// ---------------- scratch ----------------
__device__ float g_h[MROWS*DMODEL];
__device__ float g_res[MROWS*DMODEL];
__device__ float g_ff[MROWS*DFF];
__device__ float g_qk[BHN*TLEN*DHEAD];
__device__ float g_v[BHN*TLEN*DHEAD];
__device__ __half g_so16[(long)BHN*ITEMS*DHEAD];   // (bh, h, t, d)
__device__ float g_lse[BHN*ITEMS];                  // (bh, h, t)
__device__ int   g_st[BHN*ITEMS];
__device__ unsigned char g_bkt[BHN*ITEMS];
__device__ int   g_base[BHN*256];
__device__ float g_part[BSZ*HCHUNKS*3];

// ---------------- tf32 helpers ----------------
__device__ __forceinline__ uint32_t f2tf(float x) {
  uint32_t u; asm("cvt.rna.tf32.f32 %0, %1;" : "=r"(u) : "f"(x)); return u;
}
__device__ __forceinline__ void split_tf(float x, uint32_t& hi, uint32_t& lo) {
  hi = f2tf(x);
  lo = f2tf(x - __uint_as_float(hi));
}
__device__ __forceinline__ void mma_tf32(float* c, const uint32_t* a, const uint32_t* b) {
  asm volatile(
    "mma.sync.aligned.m16n8k8.row.col.f32.tf32.tf32.f32 "
    "{%0,%1,%2,%3}, {%4,%5,%6,%7}, {%8,%9}, {%0,%1,%2,%3};\n"
    : "+f"(c[0]), "+f"(c[1]), "+f"(c[2]), "+f"(c[3])
    : "r"(a[0]), "r"(a[1]), "r"(a[2]), "r"(a[3]), "r"(b[0]), "r"(b[1]));
}
__device__ __forceinline__ void mma_f16(float* c, uint32_t a0, uint32_t a1, uint32_t a2, uint32_t a3,
                                        uint32_t b0, uint32_t b1) {
  asm volatile(
    "mma.sync.aligned.m16n8k16.row.col.f32.f16.f16.f32 "
    "{%0,%1,%2,%3}, {%4,%5,%6,%7}, {%8,%9}, {%0,%1,%2,%3};\n"
    : "+f"(c[0]), "+f"(c[1]), "+f"(c[2]), "+f"(c[3])
    : "r"(a0), "r"(a1), "r"(a2), "r"(a3), "r"(b0), "r"(b1));
}

// ---------------- fast exp on FMA/ALU pipes ----------------
__device__ __forceinline__ float exp_fast(float x) {
  float z = fmaxf(x * 1.4426950408889634f, -126.f);
  float t = z + 12582912.f;
  int   i = __float_as_int(t) - 0x4B400000;
  float f = z - (t - 12582912.f);
  float p = 1.3333558146e-3f;
  p = fmaf(p, f, 9.6181291076e-3f);
  p = fmaf(p, f, 5.5504108665e-2f);
  p = fmaf(p, f, 2.4022650696e-1f);
  p = fmaf(p, f, 6.9314718056e-1f);
  p = fmaf(p, f, 1.0f);
  return __int_as_float(__float_as_int(p) + (i << 23));
}

// ---------------- embedding ----------------
__global__ void embed_kernel(const float* __restrict__ xe, const float* __restrict__ xme,
                             const float* __restrict__ xd, const float* __restrict__ xmd,
                             const float* __restrict__ convw, const float* __restrict__ tw) {
  int bt = blockIdx.x; int b = bt / TLEN; int t = bt % TLEN;
  int d = threadIdx.x;
  __shared__ float sx[3][ENCIN];
  __shared__ float sm[MARK];
  for (int i = d; i < 3*ENCIN; i += 128) {
    int k = i / ENCIN, c = i % ENCIN;
    int tt = t - 1 + k; tt = (tt + TLEN) % TLEN;
    float v = (tt < SENC) ? xe[(b*SENC + tt)*ENCIN + c]
                          : xd[(b*PRED + (tt - SENC))*ENCIN + c];
    sx[k][c] = v;
  }
  if (d < MARK)
    sm[d] = (t < SENC) ? xme[(b*SENC + t)*MARK + d]
                       : xmd[(b*PRED + (t - SENC))*MARK + d];
  __syncthreads();
  float acc = 0.f;
  #pragma unroll
  for (int k = 0; k < 3; k++)
    #pragma unroll
    for (int c = 0; c < ENCIN; c++)
      acc += sx[k][c] * convw[(k*ENCIN + c)*DMODEL + d];
  #pragma unroll
  for (int m = 0; m < MARK; m++) acc += sm[m] * tw[m*DMODEL + d];
  int i2 = (d >> 1) * 2;
  float div = expf((float)i2 * (-logf(10000.f) / (float)DMODEL));
  float ang = (float)t * div;
  acc += (d & 1) ? cosf(ang) : sinf(ang);
  g_h[(bt)*DMODEL + d] = acc;
}

#define AS_STRIDE 20
#define BS_STRIDE 136

// ---------------- error-corrected TF32x3 GEMM (qk projection) ----------------
#define QK_SMEM_WORDS 18944
__global__ void __launch_bounds__(256, 2) gemm_qk_tf32x3(
    const float* __restrict__ A, const float* __restrict__ B,
    float* __restrict__ C, int M, int N, int K) {
  extern __shared__ __align__(16) uint32_t qsm[];
  uint32_t* Ash = qsm;
  uint32_t* Asl = qsm + 5120;
  uint32_t* Bsh = qsm + 10240;
  uint32_t* Bsl = qsm + 14592;
  #define ASH(b,r,c) Ash[(b)*2560 + (r)*AS_STRIDE + (c)]
  #define ASL(b,r,c) Asl[(b)*2560 + (r)*AS_STRIDE + (c)]
  #define BSH(b,r,c) Bsh[(b)*2176 + (r)*BS_STRIDE + (c)]
  #define BSL(b,r,c) Bsl[(b)*2176 + (r)*BS_STRIDE + (c)]
  int tid = threadIdx.x;
  int warp = tid >> 5, lane = tid & 31;
  int wm = warp >> 2, wn = warp & 3;
  int m_warp = wm * 64, n_warp = wn * 32;
  int g = lane >> 2, l4 = lane & 3;
  int bm = blockIdx.y * 128, bn = blockIdx.x * 128;

  int ar = tid >> 1, ac = (tid & 1) * 8;
  int bk = tid >> 5, bnn = (tid & 31) * 4;
  const float* Ap = A + (long)(bm + ar) * K + ac;
  const float* Bp = B + (long)bk * N + bn + bnn;

  float acc[4][4][4] = {};
  int ntiles = K >> 4;
  float4 fa0, fa1, fb0, fb1;
  fa0 = *(const float4*)(Ap);
  fa1 = *(const float4*)(Ap + 4);
  fb0 = *(const float4*)(Bp);
  fb1 = *(const float4*)(Bp + 8 * (long)N);
  int buf = 0;
  for (int t = 0; t < ntiles; t++) {
    float av[8] = {fa0.x,fa0.y,fa0.z,fa0.w,fa1.x,fa1.y,fa1.z,fa1.w};
    #pragma unroll
    for (int i = 0; i < 8; i++) {
      uint32_t hi, lo; split_tf(av[i], hi, lo);
      ASH(buf, ar, ac+i) = hi; ASL(buf, ar, ac+i) = lo;
    }
    float bv0[4] = {fb0.x,fb0.y,fb0.z,fb0.w};
    float bv1[4] = {fb1.x,fb1.y,fb1.z,fb1.w};
    #pragma unroll
    for (int i = 0; i < 4; i++) {
      uint32_t hi, lo; split_tf(bv0[i], hi, lo);
      BSH(buf, bk, bnn+i) = hi; BSL(buf, bk, bnn+i) = lo;
      split_tf(bv1[i], hi, lo);
      BSH(buf, bk+8, bnn+i) = hi; BSL(buf, bk+8, bnn+i) = lo;
    }
    __syncthreads();
    if (t + 1 < ntiles) {
      fa0 = *(const float4*)(Ap + (t+1)*16);
      fa1 = *(const float4*)(Ap + (t+1)*16 + 4);
      fb0 = *(const float4*)(Bp + (long)((t+1)*16) * N);
      fb1 = *(const float4*)(Bp + (long)((t+1)*16 + 8) * N);
    }
    #pragma unroll
    for (int k8 = 0; k8 < 16; k8 += 8) {
      uint32_t ah[4][4], al[4][4], bh[4][2], bl[4][2];
      #pragma unroll
      for (int mf = 0; mf < 4; mf++) {
        int mr = m_warp + mf*16 + g;
        ah[mf][0] = ASH(buf, mr    , k8 + l4);
        ah[mf][1] = ASH(buf, mr + 8, k8 + l4);
        ah[mf][2] = ASH(buf, mr    , k8 + l4 + 4);
        ah[mf][3] = ASH(buf, mr + 8, k8 + l4 + 4);
        al[mf][0] = ASL(buf, mr    , k8 + l4);
        al[mf][1] = ASL(buf, mr + 8, k8 + l4);
        al[mf][2] = ASL(buf, mr    , k8 + l4 + 4);
        al[mf][3] = ASL(buf, mr + 8, k8 + l4 + 4);
      }
      #pragma unroll
      for (int nf = 0; nf < 4; nf++) {
        int nc = n_warp + nf*8 + g;
        bh[nf][0] = BSH(buf, k8 + l4    , nc);
        bh[nf][1] = BSH(buf, k8 + l4 + 4, nc);
        bl[nf][0] = BSL(buf, k8 + l4    , nc);
        bl[nf][1] = BSL(buf, k8 + l4 + 4, nc);
      }
      #pragma unroll
      for (int mf = 0; mf < 4; mf++)
        #pragma unroll
        for (int nf = 0; nf < 4; nf++) {
          mma_tf32(acc[mf][nf], al[mf], bh[nf]);
          mma_tf32(acc[mf][nf], ah[mf], bl[nf]);
          mma_tf32(acc[mf][nf], ah[mf], bh[nf]);
        }
    }
    buf ^= 1;
  }
  #pragma unroll
  for (int mf = 0; mf < 4; mf++) {
    #pragma unroll
    for (int hf = 0; hf < 2; hf++) {
      int r = bm + m_warp + mf*16 + g + hf*8;
      #pragma unroll
      for (int nf = 0; nf < 4; nf++) {
        int c = bn + n_warp + nf*8 + 2*l4;
        float vx = acc[mf][nf][hf*2+0];
        float vy = acc[mf][nf][hf*2+1];
        int b = r / TLEN, t = r % TLEN;
        int hd = c >> 5, dh = c & 31;
        *(float2*)&C[(((long)b*NHEADS + hd)*TLEN + t)*DHEAD + dh] = make_float2(vx, vy);
      }
    }
  }
  #undef ASH
  #undef ASL
  #undef BSH
  #undef BSL
}

// ---------------- TF32 tensor-core GEMM 128x128 ----------------
// EPI: 0 none, 1 = +bias +residual +LayerNorm, 3 = +bias +GELU
template<int EPI, int SPLIT>
__global__ void __launch_bounds__(256, 2) gemm_tf32(
    const float* __restrict__ A, const float* __restrict__ B,
    const float* __restrict__ bias, const float* __restrict__ R,
    const float* __restrict__ lng, const float* __restrict__ lnb,
    float* __restrict__ C, int M, int N, int K) {
  __shared__ uint32_t As[2][128][AS_STRIDE];
  __shared__ uint32_t Bs[2][16][BS_STRIDE];
  int tid = threadIdx.x;
  int warp = tid >> 5, lane = tid & 31;
  int wm = warp >> 2, wn = warp & 3;
  int m_warp = wm * 64, n_warp = wn * 32;
  int g = lane >> 2, l4 = lane & 3;
  int bm = blockIdx.y * 128, bn = blockIdx.x * 128;

  int ar = tid >> 1, ac = (tid & 1) * 8;
  int bk = tid >> 5, bnn = (tid & 31) * 4;
  const float* Ap = A + (long)(bm + ar) * K + ac;
  const float* Bp = B + (long)bk * N + bn + bnn;

  float acc[4][4][4] = {};
  int ntiles = K >> 4;
  float4 fa0, fa1, fb0, fb1;
  fa0 = *(const float4*)(Ap);
  fa1 = *(const float4*)(Ap + 4);
  fb0 = *(const float4*)(Bp);
  fb1 = *(const float4*)(Bp + 8 * (long)N);
  int buf = 0;
  for (int t = 0; t < ntiles; t++) {
    As[buf][ar][ac+0] = f2tf(fa0.x); As[buf][ar][ac+1] = f2tf(fa0.y);
    As[buf][ar][ac+2] = f2tf(fa0.z); As[buf][ar][ac+3] = f2tf(fa0.w);
    As[buf][ar][ac+4] = f2tf(fa1.x); As[buf][ar][ac+5] = f2tf(fa1.y);
    As[buf][ar][ac+6] = f2tf(fa1.z); As[buf][ar][ac+7] = f2tf(fa1.w);
    Bs[buf][bk][bnn+0] = f2tf(fb0.x); Bs[buf][bk][bnn+1] = f2tf(fb0.y);
    Bs[buf][bk][bnn+2] = f2tf(fb0.z); Bs[buf][bk][bnn+3] = f2tf(fb0.w);
    Bs[buf][bk+8][bnn+0] = f2tf(fb1.x); Bs[buf][bk+8][bnn+1] = f2tf(fb1.y);
    Bs[buf][bk+8][bnn+2] = f2tf(fb1.z); Bs[buf][bk+8][bnn+3] = f2tf(fb1.w);
    __syncthreads();
    if (t + 1 < ntiles) {
      fa0 = *(const float4*)(Ap + (t+1)*16);
      fa1 = *(const float4*)(Ap + (t+1)*16 + 4);
      fb0 = *(const float4*)(Bp + (long)((t+1)*16) * N);
      fb1 = *(const float4*)(Bp + (long)((t+1)*16 + 8) * N);
    }
    #pragma unroll
    for (int k8 = 0; k8 < 16; k8 += 8) {
      uint32_t afr[4][4], bfr[4][2];
      #pragma unroll
      for (int mf = 0; mf < 4; mf++) {
        int mr = m_warp + mf*16 + g;
        afr[mf][0] = As[buf][mr    ][k8 + l4];
        afr[mf][1] = As[buf][mr + 8][k8 + l4];
        afr[mf][2] = As[buf][mr    ][k8 + l4 + 4];
        afr[mf][3] = As[buf][mr + 8][k8 + l4 + 4];
      }
      #pragma unroll
      for (int nf = 0; nf < 4; nf++) {
        int nc = n_warp + nf*8 + g;
        bfr[nf][0] = Bs[buf][k8 + l4    ][nc];
        bfr[nf][1] = Bs[buf][k8 + l4 + 4][nc];
      }
      #pragma unroll
      for (int mf = 0; mf < 4; mf++)
        #pragma unroll
        for (int nf = 0; nf < 4; nf++)
          mma_tf32(acc[mf][nf], afr[mf], bfr[nf]);
    }
    buf ^= 1;
  }

  if (EPI == 1) {
    float* Ssum = (float*)As;
    float* Ssq  = ((float*)As) + 512;
    __syncthreads();
    float psum[4][2], psq[4][2];
    #pragma unroll
    for (int mf = 0; mf < 4; mf++) {
      #pragma unroll
      for (int hf = 0; hf < 2; hf++) {
        int r = bm + m_warp + mf*16 + g + hf*8;
        float s = 0.f, sq = 0.f;
        #pragma unroll
        for (int nf = 0; nf < 4; nf++) {
          int c = n_warp + nf*8 + 2*l4;
          #pragma unroll
          for (int p = 0; p < 2; p++) {
            float v = acc[mf][nf][hf*2+p] + bias[c+p] + R[(long)r*N + c + p];
            acc[mf][nf][hf*2+p] = v;
            s += v; sq += v*v;
          }
        }
        s  += __shfl_xor_sync(0xffffffffu, s, 1);
        s  += __shfl_xor_sync(0xffffffffu, s, 2);
        sq += __shfl_xor_sync(0xffffffffu, sq, 1);
        sq += __shfl_xor_sync(0xffffffffu, sq, 2);
        psum[mf][hf] = s; psq[mf][hf] = sq;
      }
    }
    if (l4 == 0) {
      #pragma unroll
      for (int mf = 0; mf < 4; mf++)
        #pragma unroll
        for (int hf = 0; hf < 2; hf++) {
          int rl = m_warp + mf*16 + g + hf*8;
          Ssum[rl*4 + wn] = psum[mf][hf];
          Ssq [rl*4 + wn] = psq[mf][hf];
        }
    }
    __syncthreads();
    #pragma unroll
    for (int mf = 0; mf < 4; mf++) {
      #pragma unroll
      for (int hf = 0; hf < 2; hf++) {
        int rl = m_warp + mf*16 + g + hf*8;
        int r = bm + rl;
        float s  = Ssum[rl*4+0] + Ssum[rl*4+1] + Ssum[rl*4+2] + Ssum[rl*4+3];
        float sq = Ssq [rl*4+0] + Ssq [rl*4+1] + Ssq [rl*4+2] + Ssq [rl*4+3];
        float mean = s * (1.f/128.f);
        float var = sq * (1.f/128.f) - mean*mean;
        float rstd = rsqrtf(var + 1e-5f);
        #pragma unroll
        for (int nf = 0; nf < 4; nf++) {
          int c = n_warp + nf*8 + 2*l4;
          float2 o;
          o.x = (acc[mf][nf][hf*2+0] - mean)*rstd*lng[c+0] + lnb[c+0];
          o.y = (acc[mf][nf][hf*2+1] - mean)*rstd*lng[c+1] + lnb[c+1];
          *(float2*)&C[(long)r*N + c] = o;
        }
      }
    }
  } else {
    #pragma unroll
    for (int mf = 0; mf < 4; mf++) {
      #pragma unroll
      for (int hf = 0; hf < 2; hf++) {
        int r = bm + m_warp + mf*16 + g + hf*8;
        #pragma unroll
        for (int nf = 0; nf < 4; nf++) {
          int c = bn + n_warp + nf*8 + 2*l4;
          float vx = acc[mf][nf][hf*2+0];
          float vy = acc[mf][nf][hf*2+1];
          if (EPI == 3) {
            vx += bias[c+0]; vy += bias[c+1];
            vx = 0.5f*vx*(1.f + erff(vx*0.70710678118f));
            vy = 0.5f*vy*(1.f + erff(vy*0.70710678118f));
          }
          if (SPLIT) {
            int b = r / TLEN, t = r % TLEN;
            int hd = c >> 5, dh = c & 31;
            *(float2*)&C[(((long)b*NHEADS + hd)*TLEN + t)*DHEAD + dh] = make_float2(vx, vy);
          } else {
            *(float2*)&C[(long)r*N + c] = make_float2(vx, vy);
          }
        }
      }
    }
  }
}

// ---------------- Wo GEMM with fused cross-hash combine ----------------
__global__ void __launch_bounds__(256, 2) gemm_wo_fused(
    const float* __restrict__ B,
    const float* __restrict__ bias, const float* __restrict__ R,
    const float* __restrict__ lng, const float* __restrict__ lnb,
    float* __restrict__ C, int M, int N, int K) {
  __shared__ uint32_t As[2][128][AS_STRIDE];
  __shared__ uint32_t Bs[2][16][BS_STRIDE];
  int tid = threadIdx.x;
  int warp = tid >> 5, lane = tid & 31;
  int wm = warp >> 2, wn = warp & 3;
  int m_warp = wm * 64, n_warp = wn * 32;
  int g = lane >> 2, l4 = lane & 3;
  int bm = blockIdx.y * 128;

  int ar = tid >> 1, ac = (tid & 1) * 8;
  int bk = tid >> 5, bnn = (tid & 31) * 4;
  int arow = bm + ar;
  int bq = arow >> 12, tq = arow & (TLEN - 1);
  const float* Bp = B + (long)bk * N + bnn;

  float acc[4][4][4] = {};
  int ntiles = K >> 4;   // 8
  float4 fb0, fb1;
  fb0 = *(const float4*)(Bp);
  fb1 = *(const float4*)(Bp + 8 * (long)N);
  int buf = 0;
  for (int t = 0; t < ntiles; t++) {
    {
      int k0 = t*16 + ac;
      int head = k0 >> 5, dh = k0 & 31;
      long rowbase = (long)((bq*NHEADS + head)*NHASH)*TLEN + tq;
      const float* lsep = g_lse + rowbase;
      float l0 = lsep[0], l1 = lsep[TLEN], l2 = lsep[2*TLEN], l3 = lsep[3*TLEN];
      float mm = fmaxf(fmaxf(l0, l1), fmaxf(l2, l3));
      float w0 = exp_fast(l0 - mm), w1 = exp_fast(l1 - mm);
      float w2 = exp_fast(l2 - mm), w3 = exp_fast(l3 - mm);
      float invw = 1.f / (w0 + w1 + w2 + w3);
      w0 *= invw; w1 *= invw; w2 *= invw; w3 *= invw;
      const __half* sop = g_so16 + rowbase*DHEAD + dh;
      uint4 u0 = *(const uint4*)(sop);
      uint4 u1 = *(const uint4*)(sop + (long)TLEN*DHEAD);
      uint4 u2 = *(const uint4*)(sop + 2L*TLEN*DHEAD);
      uint4 u3 = *(const uint4*)(sop + 3L*TLEN*DHEAD);
      const __half2* p0 = (const __half2*)&u0;
      const __half2* p1 = (const __half2*)&u1;
      const __half2* p2 = (const __half2*)&u2;
      const __half2* p3 = (const __half2*)&u3;
      #pragma unroll
      for (int i = 0; i < 4; i++) {
        float2 a0 = __half22float2(p0[i]);
        float2 a1 = __half22float2(p1[i]);
        float2 a2 = __half22float2(p2[i]);
        float2 a3 = __half22float2(p3[i]);
        float vx = w0*a0.x + w1*a1.x + w2*a2.x + w3*a3.x;
        float vy = w0*a0.y + w1*a1.y + w2*a2.y + w3*a3.y;
        As[buf][ar][ac + 2*i    ] = f2tf(vx);
        As[buf][ar][ac + 2*i + 1] = f2tf(vy);
      }
    }
    Bs[buf][bk][bnn+0] = f2tf(fb0.x); Bs[buf][bk][bnn+1] = f2tf(fb0.y);
    Bs[buf][bk][bnn+2] = f2tf(fb0.z); Bs[buf][bk][bnn+3] = f2tf(fb0.w);
    Bs[buf][bk+8][bnn+0] = f2tf(fb1.x); Bs[buf][bk+8][bnn+1] = f2tf(fb1.y);
    Bs[buf][bk+8][bnn+2] = f2tf(fb1.z); Bs[buf][bk+8][bnn+3] = f2tf(fb1.w);
    __syncthreads();
    if (t + 1 < ntiles) {
      fb0 = *(const float4*)(Bp + (long)((t+1)*16) * N);
      fb1 = *(const float4*)(Bp + (long)((t+1)*16 + 8) * N);
    }
    #pragma unroll
    for (int k8 = 0; k8 < 16; k8 += 8) {
      uint32_t afr[4][4], bfr[4][2];
      #pragma unroll
      for (int mf = 0; mf < 4; mf++) {
        int mr = m_warp + mf*16 + g;
        afr[mf][0] = As[buf][mr    ][k8 + l4];
        afr[mf][1] = As[buf][mr + 8][k8 + l4];
        afr[mf][2] = As[buf][mr    ][k8 + l4 + 4];
        afr[mf][3] = As[buf][mr + 8][k8 + l4 + 4];
      }
      #pragma unroll
      for (int nf = 0; nf < 4; nf++) {
        int nc = n_warp + nf*8 + g;
        bfr[nf][0] = Bs[buf][k8 + l4    ][nc];
        bfr[nf][1] = Bs[buf][k8 + l4 + 4][nc];
      }
      #pragma unroll
      for (int mf = 0; mf < 4; mf++)
        #pragma unroll
        for (int nf = 0; nf < 4; nf++)
          mma_tf32(acc[mf][nf], afr[mf], bfr[nf]);
    }
    buf ^= 1;
  }

  float* Ssum = (float*)As;
  float* Ssq  = ((float*)As) + 512;
  __syncthreads();
  float psum[4][2], psq[4][2];
  #pragma unroll
  for (int mf = 0; mf < 4; mf++) {
    #pragma unroll
    for (int hf = 0; hf < 2; hf++) {
      int r = bm + m_warp + mf*16 + g + hf*8;
      float s = 0.f, sq = 0.f;
      #pragma unroll
      for (int nf = 0; nf < 4; nf++) {
        int c = n_warp + nf*8 + 2*l4;
        #pragma unroll
        for (int p = 0; p < 2; p++) {
          float v = acc[mf][nf][hf*2+p] + bias[c+p] + R[(long)r*N + c + p];
          acc[mf][nf][hf*2+p] = v;
          s += v; sq += v*v;
        }
      }
      s  += __shfl_xor_sync(0xffffffffu, s, 1);
      s  += __shfl_xor_sync(0xffffffffu, s, 2);
      sq += __shfl_xor_sync(0xffffffffu, sq, 1);
      sq += __shfl_xor_sync(0xffffffffu, sq, 2);
      psum[mf][hf] = s; psq[mf][hf] = sq;
    }
  }
  if (l4 == 0) {
    #pragma unroll
    for (int mf = 0; mf < 4; mf++)
      #pragma unroll
      for (int hf = 0; hf < 2; hf++) {
        int rl = m_warp + mf*16 + g + hf*8;
        Ssum[rl*4 + wn] = psum[mf][hf];
        Ssq [rl*4 + wn] = psq[mf][hf];
      }
  }
  __syncthreads();
  #pragma unroll
  for (int mf = 0; mf < 4; mf++) {
    #pragma unroll
    for (int hf = 0; hf < 2; hf++) {
      int rl = m_warp + mf*16 + g + hf*8;
      int r = bm + rl;
      float s  = Ssum[rl*4+0] + Ssum[rl*4+1] + Ssum[rl*4+2] + Ssum[rl*4+3];
      float sq = Ssq [rl*4+0] + Ssq [rl*4+1] + Ssq [rl*4+2] + Ssq [rl*4+3];
      float mean = s * (1.f/128.f);
      float var = sq * (1.f/128.f) - mean*mean;
      float rstd = rsqrtf(var + 1e-5f);
      #pragma unroll
      for (int nf = 0; nf < 4; nf++) {
        int c = n_warp + nf*8 + 2*l4;
        float2 o;
        o.x = (acc[mf][nf][hf*2+0] - mean)*rstd*lng[c+0] + lnb[c+0];
        o.y = (acc[mf][nf][hf*2+1] - mean)*rstd*lng[c+1] + lnb[c+1];
        *(float2*)&C[(long)r*N + c] = o;
      }
    }
  }
}

// ---------------- fused rotation + argmax (R14 version) ----------------
#define ROT_ROWS 64
__global__ void __launch_bounds__(128) rot_argmax_kernel(const float* __restrict__ rot_l) {
  __shared__ __align__(16) float qT[32][ROT_ROWS + 4];
  int tid = threadIdx.x, lane = tid & 31, h = tid >> 5;
  long row0 = (long)blockIdx.x * ROT_ROWS;
  int bh = (int)(row0 >> 12);
  int t0 = (int)(row0 & (TLEN - 1));

  float rcol[32];
  #pragma unroll
  for (int d = 0; d < 32; d++) rcol[d] = rot_l[d*128 + tid];

  {
    int r = tid >> 1;
    int half = (tid & 1) * 16;
    const float* gq = g_qk + (row0 + r)*DHEAD + half;
    #pragma unroll
    for (int f = 0; f < 4; f++) {
      float4 v = *(const float4*)(gq + f*4);
      qT[half + f*4 + 0][r] = v.x; qT[half + f*4 + 1][r] = v.y;
      qT[half + f*4 + 2][r] = v.z; qT[half + f*4 + 3][r] = v.w;
    }
  }
  __syncthreads();

  unsigned char* bp = g_bkt + (bh*NHASH + h)*TLEN + t0;
  #pragma unroll 4
  for (int rg = 0; rg < ROT_ROWS/4; rg++) {
    float a0 = 0.f, a1 = 0.f, a2 = 0.f, a3 = 0.f;
    #pragma unroll
    for (int d = 0; d < 32; d++) {
      float4 q4 = *(const float4*)&qT[d][rg*4];
      float r = rcol[d];
      a0 += q4.x * r; a1 += q4.y * r; a2 += q4.z * r; a3 += q4.w * r;
    }
    #pragma unroll
    for (int rr = 0; rr < 4; rr++) {
      float v = (rr == 0) ? a0 : (rr == 1) ? a1 : (rr == 2) ? a2 : a3;
      uint32_t key = __float_as_uint(fabsf(v));
      uint32_t mx = __reduce_max_sync(0xffffffffu, key);
      bool eq = (key == mx);
      bool pos = (v >= -v);
      unsigned bpos = __ballot_sync(0xffffffffu, eq && pos);
      unsigned bneg = __ballot_sync(0xffffffffu, eq && !pos);
      int bucket = bpos ? (__ffs(bpos) - 1) : (__ffs(bneg) + 31);
      if (lane == 0) bp[rg*4 + rr] = (unsigned char)bucket;
    }
  }
}

// ---------------- counting sort: histogram + scan ----------------
__global__ void hist_kernel() {
  __shared__ int cnt[256];
  int bh = blockIdx.x, tid = threadIdx.x;
  cnt[tid] = 0; __syncthreads();
  const unsigned char* bp = g_bkt + bh*ITEMS;
  for (int i = tid; i < ITEMS; i += 256) {
    int gb = ((i >> 12) << 6) + bp[i];
    atomicAdd(&cnt[gb], 1);
  }
  __syncthreads();
  if (tid == 0) {
    int s = 0;
    #pragma unroll 8
    for (int j = 0; j < 256; j++) { g_base[bh*256 + j] = s; s += cnt[j]; }
  }
}

__global__ void __launch_bounds__(1024) place_kernel() {
  int bhh = blockIdx.x;
  int bh = bhh >> 2, h = bhh & 3;
  int warp = threadIdx.x >> 5, lane = threadIdx.x & 31;
  const unsigned char* bp = g_bkt + (bh*NHASH + h)*TLEN;
  #pragma unroll
  for (int s = 0; s < 2; s++) {
    int lb = warp*2 + s;
    int base = g_base[bh*256 + h*64 + lb];
    for (int t0 = 0; t0 < TLEN; t0 += 32) {
      int my = bp[t0 + lane];
      unsigned mask = __ballot_sync(0xffffffffu, my == lb);
      if (my == lb) {
        int p = base + __popc(mask & ((1u << lane) - 1u));
        g_st[bh*ITEMS + p] = t0 + lane;
      }
      base += __popc(mask);
    }
  }
}

// ---------------- tensor-core LSH attention: 2 chunks / CTA ----------------
// 256 threads, 8 warps. group = warp>>2: group 0 -> chunk c0=2*cp (keys j in [0,128)),
// group 1 -> chunk c1=2*cp+1 (keys j in [64,192)). Keys j=0..191 = chunks c0-1, c0, c1.
// smem (words): qS[128][36] @0 (4608) | kTd[32][200] @4608 (6400)
//               pS16 half[128][136] aliases @0 (8704 w) after dots sync
//               vS16 half[32][200] @11008 (3200 w) | sKt[192] @14208
#define ATTN_SMEM_WORDS 14400
__global__ void __launch_bounds__(256, 2) attn_kernel() {
  extern __shared__ __align__(16) uint32_t smw[];
  uint32_t* qS   = smw;                       // [128][36] tf32 (query rows of c0,c1)
  uint32_t* kTd  = smw + 4608;                // [32][200] tf32 K^T normalized
  __half*   pS16 = (__half*)smw;              // [128][136] aliases region A
  uint32_t* pW   = smw;                       // word view of pS16 (stride 68 w/row)
  __half*   vS16 = (__half*)(smw + 11008);    // [32][200] halves
  uint32_t* vW   = smw + 11008;               // word view (stride 100 w/row)
  int* sKt = (int*)(smw + 14208);             // [192]

  int bh = blockIdx.x >> 7;
  int cp = blockIdx.x & 127;
  int c0 = cp * 2;
  int hh = c0 >> 6;                           // same hash for c0 and c1
  int tid = threadIdx.x;
  int lane = tid & 31, warp = tid >> 5;
  int group = warp >> 2, wg = warp & 3;
  int g = lane >> 2, l4 = lane & 3;

  if (tid < 192) {
    int p = (c0*64 + tid + ITEMS - 64) & (ITEMS - 1);
    sKt[tid] = g_st[bh*ITEMS + p];
  }
  __syncthreads();

  if (tid < 192) {
    int j = tid;
    int t = sKt[j];
    const float* gk = g_qk + ((long)bh*TLEN + t)*DHEAD;
    const float* gv = g_v  + ((long)bh*TLEN + t)*DHEAD;
    float4 kr[8];
    float ss = 0.f;
    #pragma unroll
    for (int f = 0; f < 8; f++) {
      kr[f] = *(const float4*)(gk + f*4);
      ss += kr[f].x*kr[f].x + kr[f].y*kr[f].y + kr[f].z*kr[f].z + kr[f].w*kr[f].w;
    }
    if (j >= 64) {                 // query row (c0 rows: j 64..127 -> q 0..63; c1: 128..191 -> q 64..127)
      int qr = j - 64;
      #pragma unroll
      for (int f = 0; f < 8; f++) {
        uint4 u;
        u.x = f2tf(kr[f].x); u.y = f2tf(kr[f].y); u.z = f2tf(kr[f].z); u.w = f2tf(kr[f].w);
        *(uint4*)&qS[qr*36 + f*4] = u;
      }
    }
    float inv = ATTN_SCALE / fmaxf(sqrtf(ss), 1e-12f);
    #pragma unroll
    for (int f = 0; f < 8; f++) {
      kTd[(f*4+0)*200 + j] = f2tf(kr[f].x * inv);
      kTd[(f*4+1)*200 + j] = f2tf(kr[f].y * inv);
      kTd[(f*4+2)*200 + j] = f2tf(kr[f].z * inv);
      kTd[(f*4+3)*200 + j] = f2tf(kr[f].w * inv);
    }
    #pragma unroll
    for (int f = 0; f < 8; f++) {
      float4 vv = *(const float4*)(gv + f*4);
      vS16[(f*4+0)*200 + j] = __float2half_rn(vv.x);
      vS16[(f*4+1)*200 + j] = __float2half_rn(vv.y);
      vS16[(f*4+2)*200 + j] = __float2half_rn(vv.z);
      vS16[(f*4+3)*200 + j] = __float2half_rn(vv.w);
    }
  }
  __syncthreads();

  // ---- dots: S = Q*K^T over this group's 128-key window ----
  int qbase = group*64 + wg*16;     // query row block in qS space (0..127)
  int joff  = group*64;             // key window start (0 or 64)
  float s[16][4];
  #pragma unroll
  for (int nt = 0; nt < 16; nt++)
    #pragma unroll
    for (int p = 0; p < 4; p++) s[nt][p] = 0.f;
  #pragma unroll
  for (int k8 = 0; k8 < 32; k8 += 8) {
    uint32_t afr[4];
    afr[0] = qS[(qbase + g    )*36 + k8 + l4];
    afr[1] = qS[(qbase + g + 8)*36 + k8 + l4];
    afr[2] = qS[(qbase + g    )*36 + k8 + l4 + 4];
    afr[3] = qS[(qbase + g + 8)*36 + k8 + l4 + 4];
    #pragma unroll
    for (int nt = 0; nt < 16; nt++) {
      uint32_t bfr[2];
      bfr[0] = kTd[(k8 + l4    )*200 + joff + nt*8 + g];
      bfr[1] = kTd[(k8 + l4 + 4)*200 + joff + nt*8 + g];
      mma_tf32(s[nt], afr, bfr);
    }
  }
  __syncthreads();   // ALL warps done reading qS/kTd -> pS16 may alias

  // ---- self-mask + softmax; write P (fp16, per-warp rows only) ----
  int r0 = qbase + g, r1 = qbase + g + 8;      // qS-row space
  int qt0 = sKt[64 + r0], qt1 = sKt[64 + r1];
  float m0 = -1e30f, m1 = -1e30f;
  #pragma unroll
  for (int nt = 0; nt < 16; nt++) {
    int j0 = nt*8 + 2*l4;
    int kt0 = sKt[joff + j0], kt1 = sKt[joff + j0 + 1];
    if (kt0 == qt0) s[nt][0] = -5e4f;
    if (kt1 == qt0) s[nt][1] = -5e4f;
    if (kt0 == qt1) s[nt][2] = -5e4f;
    if (kt1 == qt1) s[nt][3] = -5e4f;
    m0 = fmaxf(m0, fmaxf(s[nt][0], s[nt][1]));
    m1 = fmaxf(m1, fmaxf(s[nt][2], s[nt][3]));
  }
  m0 = fmaxf(m0, __shfl_xor_sync(0xffffffffu, m0, 1));
  m0 = fmaxf(m0, __shfl_xor_sync(0xffffffffu, m0, 2));
  m1 = fmaxf(m1, __shfl_xor_sync(0xffffffffu, m1, 1));
  m1 = fmaxf(m1, __shfl_xor_sync(0xffffffffu, m1, 2));
  float sum0 = 0.f, sum1 = 0.f;
  #pragma unroll
  for (int nt = 0; nt < 16; nt++) {
    int j0 = nt*8 + 2*l4;
    __half h00 = __float2half_rn(exp_fast(s[nt][0] - m0));
    __half h01 = __float2half_rn(exp_fast(s[nt][1] - m0));
    __half h10 = __float2half_rn(exp_fast(s[nt][2] - m1));
    __half h11 = __float2half_rn(exp_fast(s[nt][3] - m1));
    sum0 += __half2float(h00) + __half2float(h01);
    sum1 += __half2float(h10) + __half2float(h11);
    __half2 v0; v0.x = h00; v0.y = h01;
    __half2 v1; v1.x = h10; v1.y = h11;
    *(__half2*)&pS16[r0*136 + j0] = v0;
    *(__half2*)&pS16[r1*136 + j0] = v1;
  }
  sum0 += __shfl_xor_sync(0xffffffffu, sum0, 1);
  sum0 += __shfl_xor_sync(0xffffffffu, sum0, 2);
  sum1 += __shfl_xor_sync(0xffffffffu, sum1, 1);
  sum1 += __shfl_xor_sync(0xffffffffu, sum1, 2);
  long lbase = (long)(bh*NHASH + hh)*TLEN;
  if (l4 == 0) {
    g_lse[lbase + qt0] = m0 + __logf(sum0);
    g_lse[lbase + qt1] = m1 + __logf(sum1);
  }
  __syncwarp();     // pS16 rows are per-warp

  // ---- PV: O = P*V, fp16 mma m16n8k16, k over this group's 128 keys ----
  float o[4][4];
  #pragma unroll
  for (int nt = 0; nt < 4; nt++)
    #pragma unroll
    for (int p = 0; p < 4; p++) o[nt][p] = 0.f;
  #pragma unroll
  for (int k16 = 0; k16 < 128; k16 += 16) {
    uint32_t a0 = pW[r0*68 + k16/2 + l4];
    uint32_t a1 = pW[r1*68 + k16/2 + l4];
    uint32_t a2 = pW[r0*68 + k16/2 + 4 + l4];
    uint32_t a3 = pW[r1*68 + k16/2 + 4 + l4];
    #pragma unroll
    for (int nt = 0; nt < 4; nt++) {
      uint32_t b0 = vW[(nt*8 + g)*100 + (joff + k16)/2 + l4];
      uint32_t b1 = vW[(nt*8 + g)*100 + (joff + k16)/2 + 4 + l4];
      mma_f16(o[nt], a0, a1, a2, a3, b0, b1);
    }
  }
  float inv0 = 1.f / sum0, inv1 = 1.f / sum1;
  __half* outp = g_so16 + lbase*DHEAD;
  #pragma unroll
  for (int nt = 0; nt < 4; nt++) {
    int d0 = nt*8 + 2*l4;
    *(__half2*)&outp[(long)qt0*DHEAD + d0] = __floats2half2_rn(o[nt][0]*inv0, o[nt][1]*inv0);
    *(__half2*)&outp[(long)qt1*DHEAD + d0] = __floats2half2_rn(o[nt][2]*inv1, o[nt][3]*inv1);
  }
}

// ---------------- final layernorm, tail rows only ----------------
__global__ void ln_tail_kernel(const float* __restrict__ in, float* __restrict__ out,
                               const float* __restrict__ g, const float* __restrict__ bb) {
  int idx = blockIdx.x;
  int b = idx >> 10, tt = idx & (PRED - 1);
  long row = (long)b*TLEN + SENC + tt;
  int d = threadIdx.x;
  __shared__ float red[4];
  float x = in[row*DMODEL + d];
  float s = x;
  #pragma unroll
  for (int off = 16; off; off >>= 1) s += __shfl_xor_sync(0xffffffffu, s, off);
  if ((d & 31) == 0) red[d >> 5] = s;
  __syncthreads();
  float mean = (red[0]+red[1]+red[2]+red[3]) * (1.f/DMODEL);
  float dv = x - mean;
  float s2 = dv*dv;
  #pragma unroll
  for (int off = 16; off; off >>= 1) s2 += __shfl_xor_sync(0xffffffffu, s2, off);
  __syncthreads();
  if ((d & 31) == 0) red[d >> 5] = s2;
  __syncthreads();
  float var = (red[0]+red[1]+red[2]+red[3]) * (1.f/DMODEL);
  out[row*DMODEL + d] = dv * rsqrtf(var + 1e-5f) * g[d] + bb[d];
}

// ---------------- head: parallel partial logits ----------------
__global__ void head_part_kernel(const float* __restrict__ projw, const float* __restrict__ projb,
                                 const float* __restrict__ fcw) {
  int b = blockIdx.x, chunk = blockIdx.y;
  int tid = threadIdx.x;
  int tt = chunk * 64 + tid;
  const float* hh = g_res + ((long)b*TLEN + SENC + tt)*DMODEL;
  float o4[4];
  #pragma unroll
  for (int cc = 0; cc < 4; cc++) {
    float a = projb[cc];
    #pragma unroll 8
    for (int d = 0; d < DMODEL; d++) a += hh[d]*projw[d*4 + cc];
    o4[cc] = a;
  }
  float lg0 = 0.f, lg1 = 0.f, lg2 = 0.f;
  #pragma unroll
  for (int cc = 0; cc < 4; cc++) {
    int idx = (tt*4 + cc)*3;
    lg0 += o4[cc]*fcw[idx+0];
    lg1 += o4[cc]*fcw[idx+1];
    lg2 += o4[cc]*fcw[idx+2];
  }
  __shared__ float red[3][64];
  red[0][tid] = lg0; red[1][tid] = lg1; red[2][tid] = lg2;
  __syncthreads();
  for (int off = 32; off; off >>= 1) {
    if (tid < off) {
      red[0][tid] += red[0][tid+off];
      red[1][tid] += red[1][tid+off];
      red[2][tid] += red[2][tid+off];
    }
    __syncthreads();
  }
  if (tid == 0) {
    g_part[(b*HCHUNKS + chunk)*3 + 0] = red[0][0];
    g_part[(b*HCHUNKS + chunk)*3 + 1] = red[1][0];
    g_part[(b*HCHUNKS + chunk)*3 + 2] = red[2][0];
  }
}

__global__ void head_finish_kernel(const float* __restrict__ fcb, float* __restrict__ dout) {
  int b = threadIdx.x;
  if (b >= BSZ) return;
  float l0 = fcb[0], l1 = fcb[1], l2 = fcb[2];
  for (int c = 0; c < HCHUNKS; c++) {
    l0 += g_part[(b*HCHUNKS + c)*3 + 0];
    l1 += g_part[(b*HCHUNKS + c)*3 + 1];
    l2 += g_part[(b*HCHUNKS + c)*3 + 2];
  }
  float mx = fmaxf(l0, fmaxf(l1, l2));
  float e0 = expf(l0-mx), e1 = expf(l1-mx), e2 = expf(l2-mx);
  float is = 1.f/(e0+e1+e2);
  dout[b*3+0] = e0*is; dout[b*3+1] = e1*is; dout[b*3+2] = e2*is;
}

// ---------------- host launch ----------------
extern "C" void kernel_launch(void* const* d_in, const int* in_sizes, int n_in,
                              void* d_out, int out_size) {
  const float* x_enc      = (const float*)d_in[0];
  const float* x_mark_enc = (const float*)d_in[1];
  const float* x_dec      = (const float*)d_in[2];
  const float* x_mark_dec = (const float*)d_in[3];
  const float* conv_w     = (const float*)d_in[4];
  const float* timef_w    = (const float*)d_in[5];
  const float* Wqk        = (const float*)d_in[6];
  const float* Wv         = (const float*)d_in[7];
  const float* Wo         = (const float*)d_in[8];
  const float* bo         = (const float*)d_in[9];
  const float* rot        = (const float*)d_in[10];
  const float* ln1_g      = (const float*)d_in[11];
  const float* ln1_b      = (const float*)d_in[12];
  const float* ln2_g      = (const float*)d_in[13];
  const float* ln2_b      = (const float*)d_in[14];
  const float* w1         = (const float*)d_in[15];
  const float* b1         = (const float*)d_in[16];
  const float* w2         = (const float*)d_in[17];
  const float* b2         = (const float*)d_in[18];
  const float* lnf_g      = (const float*)d_in[19];
  const float* lnf_b      = (const float*)d_in[20];
  const float* proj_w     = (const float*)d_in[21];
  const float* proj_b     = (const float*)d_in[22];
  const float* fc1_w      = (const float*)d_in[23];
  const float* fc1_b      = (const float*)d_in[24];
  (void)in_sizes; (void)n_in; (void)out_size;

  void* p;
  cudaGetSymbolAddress(&p, g_h);    float* ph    = (float*)p;
  cudaGetSymbolAddress(&p, g_res);  float* pres  = (float*)p;
  cudaGetSymbolAddress(&p, g_ff);   float* pff   = (float*)p;
  cudaGetSymbolAddress(&p, g_qk);   float* pqk   = (float*)p;
  cudaGetSymbolAddress(&p, g_v);    float* pv    = (float*)p;

  const int attn_smem = ATTN_SMEM_WORDS * 4;
  cudaFuncSetAttribute(attn_kernel, cudaFuncAttributeMaxDynamicSharedMemorySize, attn_smem);
  const int qk_smem = QK_SMEM_WORDS * 4;
  cudaFuncSetAttribute(gemm_qk_tf32x3, cudaFuncAttributeMaxDynamicSharedMemorySize, qk_smem);

  embed_kernel<<<MROWS, 128>>>(x_enc, x_mark_enc, x_dec, x_mark_dec, conv_w, timef_w);

  for (int l = 0; l < NLAYERS; l++) {
    const float* Wqk_l = Wqk + (long)l*DMODEL*DMODEL;
    const float* Wv_l  = Wv  + (long)l*DMODEL*DMODEL;
    const float* Wo_l  = Wo  + (long)l*DMODEL*DMODEL;
    const float* bo_l  = bo  + l*DMODEL;
    const float* rot_l = rot + (long)l*DHEAD*NHASH*(NBUCK/2);
    const float* w1_l  = w1 + (long)l*DMODEL*DFF;
    const float* b1_l  = b1 + l*DFF;
    const float* w2_l  = w2 + (long)l*DFF*DMODEL;
    const float* b2_l  = b2 + l*DMODEL;

    gemm_qk_tf32x3<<<dim3(1,256), 256, qk_smem>>>(ph, Wqk_l, pqk, MROWS, DMODEL, DMODEL);
    gemm_tf32<0,1><<<dim3(1,256), 256>>>(ph, Wv_l, nullptr, nullptr, nullptr, nullptr, pv, MROWS, DMODEL, DMODEL);

    rot_argmax_kernel<<<BHN*TLEN/ROT_ROWS, 128>>>(rot_l);

    hist_kernel<<<BHN, 256>>>();
    place_kernel<<<BHN*NHASH, 1024>>>();

    attn_kernel<<<BHN*(NCHUNK/2), 256, attn_smem>>>();

    gemm_wo_fused<<<dim3(1,256), 256>>>(Wo_l, bo_l, ph, ln1_g + l*DMODEL, ln1_b + l*DMODEL,
                                        ph, MROWS, DMODEL, DMODEL);
    gemm_tf32<3,0><<<dim3(4,256), 256>>>(ph, w1_l, b1_l, nullptr, nullptr, nullptr, pff, MROWS, DFF, DMODEL);
    gemm_tf32<1,0><<<dim3(1,256), 256>>>(pff, w2_l, b2_l, ph, ln2_g + l*DMODEL, ln2_b + l*DMODEL,
                                         ph, MROWS, DMODEL, DFF);
  }

  ln_tail_kernel<<<BSZ*PRED, 128>>>(ph, pres, lnf_g, lnf_b);
  head_part_kernel<<<dim3(BSZ, HCHUNKS), 64>>>(proj_w, proj_b, fc1_w);
  head_finish_kernel<<<1, 32>>>(fc1_b, (float*)d_out);
}

// round 17
// speedup vs baseline: 1.0973x; 1.0327x over previous
#include <cuda_runtime.h>
#include <cuda_fp16.h>
#include <math.h>
#include <stdint.h>

// ---------------- problem constants ----------------
#define BSZ     8
#define SENC    3072
#define PRED    1024
#define ENCIN   40
#define DMODEL  128
#define NHEADS  4
#define DHEAD   32
#define NHASH   4
#define NBUCK   64
#define BUCKETSZ 64
#define NLAYERS 2
#define DFF     512
#define COUT    4
#define NCLASS  3
#define MARK    4
#define TLEN    4096
#define BHN     (BSZ*NHEADS)          // 32
#define MROWS   (BSZ*TLEN)            // 32768
#define NCHUNK  (NHASH*TLEN/BUCKETSZ) // 256
#define ITEMS   (NHASH*TLEN)          // 16384 per bh
#define ATTN_SCALE 0.17677669529663689f
#define HCHUNKS 16

// ---------------- scratch ----------------
__device__ float g_h[MROWS*DMODEL];
__device__ float g_res[MROWS*DMODEL];
__device__ float g_ff[MROWS*DFF];
__device__ float g_qk[BHN*TLEN*DHEAD];
__device__ float g_v[BHN*TLEN*DHEAD];
__device__ __half g_so16[(long)BHN*ITEMS*DHEAD];   // (bh, h, t, d)
__device__ float g_lse[BHN*ITEMS];                  // (bh, h, t)
__device__ int   g_st[BHN*ITEMS];
__device__ unsigned char g_bkt[BHN*ITEMS];
__device__ int   g_base[BHN*256];
__device__ float g_part[BSZ*HCHUNKS*3];

// ---------------- tf32 helpers ----------------
__device__ __forceinline__ uint32_t f2tf(float x) {
  uint32_t u; asm("cvt.rna.tf32.f32 %0, %1;" : "=r"(u) : "f"(x)); return u;
}
__device__ __forceinline__ void split_tf(float x, uint32_t& hi, uint32_t& lo) {
  hi = f2tf(x);
  lo = f2tf(x - __uint_as_float(hi));
}
__device__ __forceinline__ void mma_tf32(float* c, const uint32_t* a, const uint32_t* b) {
  asm volatile(
    "mma.sync.aligned.m16n8k8.row.col.f32.tf32.tf32.f32 "
    "{%0,%1,%2,%3}, {%4,%5,%6,%7}, {%8,%9}, {%0,%1,%2,%3};\n"
    : "+f"(c[0]), "+f"(c[1]), "+f"(c[2]), "+f"(c[3])
    : "r"(a[0]), "r"(a[1]), "r"(a[2]), "r"(a[3]), "r"(b[0]), "r"(b[1]));
}
__device__ __forceinline__ void mma_f16(float* c, uint32_t a0, uint32_t a1, uint32_t a2, uint32_t a3,
                                        uint32_t b0, uint32_t b1) {
  asm volatile(
    "mma.sync.aligned.m16n8k16.row.col.f32.f16.f16.f32 "
    "{%0,%1,%2,%3}, {%4,%5,%6,%7}, {%8,%9}, {%0,%1,%2,%3};\n"
    : "+f"(c[0]), "+f"(c[1]), "+f"(c[2]), "+f"(c[3])
    : "r"(a0), "r"(a1), "r"(a2), "r"(a3), "r"(b0), "r"(b1));
}

// ---------------- fast exp on FMA/ALU pipes ----------------
__device__ __forceinline__ float exp_fast(float x) {
  float z = fmaxf(x * 1.4426950408889634f, -126.f);
  float t = z + 12582912.f;
  int   i = __float_as_int(t) - 0x4B400000;
  float f = z - (t - 12582912.f);
  float p = 1.3333558146e-3f;
  p = fmaf(p, f, 9.6181291076e-3f);
  p = fmaf(p, f, 5.5504108665e-2f);
  p = fmaf(p, f, 2.4022650696e-1f);
  p = fmaf(p, f, 6.9314718056e-1f);
  p = fmaf(p, f, 1.0f);
  return __int_as_float(__float_as_int(p) + (i << 23));
}

// ---------------- embedding ----------------
__global__ void embed_kernel(const float* __restrict__ xe, const float* __restrict__ xme,
                             const float* __restrict__ xd, const float* __restrict__ xmd,
                             const float* __restrict__ convw, const float* __restrict__ tw) {
  int bt = blockIdx.x; int b = bt / TLEN; int t = bt % TLEN;
  int d = threadIdx.x;
  __shared__ float sx[3][ENCIN];
  __shared__ float sm[MARK];
  for (int i = d; i < 3*ENCIN; i += 128) {
    int k = i / ENCIN, c = i % ENCIN;
    int tt = t - 1 + k; tt = (tt + TLEN) % TLEN;
    float v = (tt < SENC) ? xe[(b*SENC + tt)*ENCIN + c]
                          : xd[(b*PRED + (tt - SENC))*ENCIN + c];
    sx[k][c] = v;
  }
  if (d < MARK)
    sm[d] = (t < SENC) ? xme[(b*SENC + t)*MARK + d]
                       : xmd[(b*PRED + (t - SENC))*MARK + d];
  __syncthreads();
  float acc = 0.f;
  #pragma unroll
  for (int k = 0; k < 3; k++)
    #pragma unroll
    for (int c = 0; c < ENCIN; c++)
      acc += sx[k][c] * convw[(k*ENCIN + c)*DMODEL + d];
  #pragma unroll
  for (int m = 0; m < MARK; m++) acc += sm[m] * tw[m*DMODEL + d];
  int i2 = (d >> 1) * 2;
  float div = expf((float)i2 * (-logf(10000.f) / (float)DMODEL));
  float ang = (float)t * div;
  acc += (d & 1) ? cosf(ang) : sinf(ang);
  g_h[(bt)*DMODEL + d] = acc;
}

#define AS_STRIDE 20
#define BS_STRIDE 136

// ---------------- error-corrected TF32x3 GEMM (qk projection) ----------------
#define QK_SMEM_WORDS 18944
__global__ void __launch_bounds__(256, 2) gemm_qk_tf32x3(
    const float* __restrict__ A, const float* __restrict__ B,
    float* __restrict__ C, int M, int N, int K) {
  extern __shared__ __align__(16) uint32_t qsm[];
  uint32_t* Ash = qsm;
  uint32_t* Asl = qsm + 5120;
  uint32_t* Bsh = qsm + 10240;
  uint32_t* Bsl = qsm + 14592;
  #define ASH(b,r,c) Ash[(b)*2560 + (r)*AS_STRIDE + (c)]
  #define ASL(b,r,c) Asl[(b)*2560 + (r)*AS_STRIDE + (c)]
  #define BSH(b,r,c) Bsh[(b)*2176 + (r)*BS_STRIDE + (c)]
  #define BSL(b,r,c) Bsl[(b)*2176 + (r)*BS_STRIDE + (c)]
  int tid = threadIdx.x;
  int warp = tid >> 5, lane = tid & 31;
  int wm = warp >> 2, wn = warp & 3;
  int m_warp = wm * 64, n_warp = wn * 32;
  int g = lane >> 2, l4 = lane & 3;
  int bm = blockIdx.y * 128, bn = blockIdx.x * 128;

  int ar = tid >> 1, ac = (tid & 1) * 8;
  int bk = tid >> 5, bnn = (tid & 31) * 4;
  const float* Ap = A + (long)(bm + ar) * K + ac;
  const float* Bp = B + (long)bk * N + bn + bnn;

  float acc[4][4][4] = {};
  int ntiles = K >> 4;
  float4 fa0, fa1, fb0, fb1;
  fa0 = *(const float4*)(Ap);
  fa1 = *(const float4*)(Ap + 4);
  fb0 = *(const float4*)(Bp);
  fb1 = *(const float4*)(Bp + 8 * (long)N);
  int buf = 0;
  for (int t = 0; t < ntiles; t++) {
    float av[8] = {fa0.x,fa0.y,fa0.z,fa0.w,fa1.x,fa1.y,fa1.z,fa1.w};
    #pragma unroll
    for (int i = 0; i < 8; i++) {
      uint32_t hi, lo; split_tf(av[i], hi, lo);
      ASH(buf, ar, ac+i) = hi; ASL(buf, ar, ac+i) = lo;
    }
    float bv0[4] = {fb0.x,fb0.y,fb0.z,fb0.w};
    float bv1[4] = {fb1.x,fb1.y,fb1.z,fb1.w};
    #pragma unroll
    for (int i = 0; i < 4; i++) {
      uint32_t hi, lo; split_tf(bv0[i], hi, lo);
      BSH(buf, bk, bnn+i) = hi; BSL(buf, bk, bnn+i) = lo;
      split_tf(bv1[i], hi, lo);
      BSH(buf, bk+8, bnn+i) = hi; BSL(buf, bk+8, bnn+i) = lo;
    }
    __syncthreads();
    if (t + 1 < ntiles) {
      fa0 = *(const float4*)(Ap + (t+1)*16);
      fa1 = *(const float4*)(Ap + (t+1)*16 + 4);
      fb0 = *(const float4*)(Bp + (long)((t+1)*16) * N);
      fb1 = *(const float4*)(Bp + (long)((t+1)*16 + 8) * N);
    }
    #pragma unroll
    for (int k8 = 0; k8 < 16; k8 += 8) {
      uint32_t ah[4][4], al[4][4], bh[4][2], bl[4][2];
      #pragma unroll
      for (int mf = 0; mf < 4; mf++) {
        int mr = m_warp + mf*16 + g;
        ah[mf][0] = ASH(buf, mr    , k8 + l4);
        ah[mf][1] = ASH(buf, mr + 8, k8 + l4);
        ah[mf][2] = ASH(buf, mr    , k8 + l4 + 4);
        ah[mf][3] = ASH(buf, mr + 8, k8 + l4 + 4);
        al[mf][0] = ASL(buf, mr    , k8 + l4);
        al[mf][1] = ASL(buf, mr + 8, k8 + l4);
        al[mf][2] = ASL(buf, mr    , k8 + l4 + 4);
        al[mf][3] = ASL(buf, mr + 8, k8 + l4 + 4);
      }
      #pragma unroll
      for (int nf = 0; nf < 4; nf++) {
        int nc = n_warp + nf*8 + g;
        bh[nf][0] = BSH(buf, k8 + l4    , nc);
        bh[nf][1] = BSH(buf, k8 + l4 + 4, nc);
        bl[nf][0] = BSL(buf, k8 + l4    , nc);
        bl[nf][1] = BSL(buf, k8 + l4 + 4, nc);
      }
      #pragma unroll
      for (int mf = 0; mf < 4; mf++)
        #pragma unroll
        for (int nf = 0; nf < 4; nf++) {
          mma_tf32(acc[mf][nf], al[mf], bh[nf]);
          mma_tf32(acc[mf][nf], ah[mf], bl[nf]);
          mma_tf32(acc[mf][nf], ah[mf], bh[nf]);
        }
    }
    buf ^= 1;
  }
  #pragma unroll
  for (int mf = 0; mf < 4; mf++) {
    #pragma unroll
    for (int hf = 0; hf < 2; hf++) {
      int r = bm + m_warp + mf*16 + g + hf*8;
      #pragma unroll
      for (int nf = 0; nf < 4; nf++) {
        int c = bn + n_warp + nf*8 + 2*l4;
        float vx = acc[mf][nf][hf*2+0];
        float vy = acc[mf][nf][hf*2+1];
        int b = r / TLEN, t = r % TLEN;
        int hd = c >> 5, dh = c & 31;
        *(float2*)&C[(((long)b*NHEADS + hd)*TLEN + t)*DHEAD + dh] = make_float2(vx, vy);
      }
    }
  }
  #undef ASH
  #undef ASL
  #undef BSH
  #undef BSL
}

// ---------------- TF32 tensor-core GEMM 128x128 ----------------
// EPI: 0 none, 1 = +bias +residual +LayerNorm, 3 = +bias +GELU
template<int EPI, int SPLIT>
__global__ void __launch_bounds__(256, 2) gemm_tf32(
    const float* __restrict__ A, const float* __restrict__ B,
    const float* __restrict__ bias, const float* __restrict__ R,
    const float* __restrict__ lng, const float* __restrict__ lnb,
    float* __restrict__ C, int M, int N, int K) {
  __shared__ uint32_t As[2][128][AS_STRIDE];
  __shared__ uint32_t Bs[2][16][BS_STRIDE];
  int tid = threadIdx.x;
  int warp = tid >> 5, lane = tid & 31;
  int wm = warp >> 2, wn = warp & 3;
  int m_warp = wm * 64, n_warp = wn * 32;
  int g = lane >> 2, l4 = lane & 3;
  int bm = blockIdx.y * 128, bn = blockIdx.x * 128;

  int ar = tid >> 1, ac = (tid & 1) * 8;
  int bk = tid >> 5, bnn = (tid & 31) * 4;
  const float* Ap = A + (long)(bm + ar) * K + ac;
  const float* Bp = B + (long)bk * N + bn + bnn;

  float acc[4][4][4] = {};
  int ntiles = K >> 4;
  float4 fa0, fa1, fb0, fb1;
  fa0 = *(const float4*)(Ap);
  fa1 = *(const float4*)(Ap + 4);
  fb0 = *(const float4*)(Bp);
  fb1 = *(const float4*)(Bp + 8 * (long)N);
  int buf = 0;
  for (int t = 0; t < ntiles; t++) {
    As[buf][ar][ac+0] = f2tf(fa0.x); As[buf][ar][ac+1] = f2tf(fa0.y);
    As[buf][ar][ac+2] = f2tf(fa0.z); As[buf][ar][ac+3] = f2tf(fa0.w);
    As[buf][ar][ac+4] = f2tf(fa1.x); As[buf][ar][ac+5] = f2tf(fa1.y);
    As[buf][ar][ac+6] = f2tf(fa1.z); As[buf][ar][ac+7] = f2tf(fa1.w);
    Bs[buf][bk][bnn+0] = f2tf(fb0.x); Bs[buf][bk][bnn+1] = f2tf(fb0.y);
    Bs[buf][bk][bnn+2] = f2tf(fb0.z); Bs[buf][bk][bnn+3] = f2tf(fb0.w);
    Bs[buf][bk+8][bnn+0] = f2tf(fb1.x); Bs[buf][bk+8][bnn+1] = f2tf(fb1.y);
    Bs[buf][bk+8][bnn+2] = f2tf(fb1.z); Bs[buf][bk+8][bnn+3] = f2tf(fb1.w);
    __syncthreads();
    if (t + 1 < ntiles) {
      fa0 = *(const float4*)(Ap + (t+1)*16);
      fa1 = *(const float4*)(Ap + (t+1)*16 + 4);
      fb0 = *(const float4*)(Bp + (long)((t+1)*16) * N);
      fb1 = *(const float4*)(Bp + (long)((t+1)*16 + 8) * N);
    }
    #pragma unroll
    for (int k8 = 0; k8 < 16; k8 += 8) {
      uint32_t afr[4][4], bfr[4][2];
      #pragma unroll
      for (int mf = 0; mf < 4; mf++) {
        int mr = m_warp + mf*16 + g;
        afr[mf][0] = As[buf][mr    ][k8 + l4];
        afr[mf][1] = As[buf][mr + 8][k8 + l4];
        afr[mf][2] = As[buf][mr    ][k8 + l4 + 4];
        afr[mf][3] = As[buf][mr + 8][k8 + l4 + 4];
      }
      #pragma unroll
      for (int nf = 0; nf < 4; nf++) {
        int nc = n_warp + nf*8 + g;
        bfr[nf][0] = Bs[buf][k8 + l4    ][nc];
        bfr[nf][1] = Bs[buf][k8 + l4 + 4][nc];
      }
      #pragma unroll
      for (int mf = 0; mf < 4; mf++)
        #pragma unroll
        for (int nf = 0; nf < 4; nf++)
          mma_tf32(acc[mf][nf], afr[mf], bfr[nf]);
    }
    buf ^= 1;
  }

  if (EPI == 1) {
    float* Ssum = (float*)As;
    float* Ssq  = ((float*)As) + 512;
    __syncthreads();
    float psum[4][2], psq[4][2];
    #pragma unroll
    for (int mf = 0; mf < 4; mf++) {
      #pragma unroll
      for (int hf = 0; hf < 2; hf++) {
        int r = bm + m_warp + mf*16 + g + hf*8;
        float s = 0.f, sq = 0.f;
        #pragma unroll
        for (int nf = 0; nf < 4; nf++) {
          int c = n_warp + nf*8 + 2*l4;
          #pragma unroll
          for (int p = 0; p < 2; p++) {
            float v = acc[mf][nf][hf*2+p] + bias[c+p] + R[(long)r*N + c + p];
            acc[mf][nf][hf*2+p] = v;
            s += v; sq += v*v;
          }
        }
        s  += __shfl_xor_sync(0xffffffffu, s, 1);
        s  += __shfl_xor_sync(0xffffffffu, s, 2);
        sq += __shfl_xor_sync(0xffffffffu, sq, 1);
        sq += __shfl_xor_sync(0xffffffffu, sq, 2);
        psum[mf][hf] = s; psq[mf][hf] = sq;
      }
    }
    if (l4 == 0) {
      #pragma unroll
      for (int mf = 0; mf < 4; mf++)
        #pragma unroll
        for (int hf = 0; hf < 2; hf++) {
          int rl = m_warp + mf*16 + g + hf*8;
          Ssum[rl*4 + wn] = psum[mf][hf];
          Ssq [rl*4 + wn] = psq[mf][hf];
        }
    }
    __syncthreads();
    #pragma unroll
    for (int mf = 0; mf < 4; mf++) {
      #pragma unroll
      for (int hf = 0; hf < 2; hf++) {
        int rl = m_warp + mf*16 + g + hf*8;
        int r = bm + rl;
        float s  = Ssum[rl*4+0] + Ssum[rl*4+1] + Ssum[rl*4+2] + Ssum[rl*4+3];
        float sq = Ssq [rl*4+0] + Ssq [rl*4+1] + Ssq [rl*4+2] + Ssq [rl*4+3];
        float mean = s * (1.f/128.f);
        float var = sq * (1.f/128.f) - mean*mean;
        float rstd = rsqrtf(var + 1e-5f);
        #pragma unroll
        for (int nf = 0; nf < 4; nf++) {
          int c = n_warp + nf*8 + 2*l4;
          float2 o;
          o.x = (acc[mf][nf][hf*2+0] - mean)*rstd*lng[c+0] + lnb[c+0];
          o.y = (acc[mf][nf][hf*2+1] - mean)*rstd*lng[c+1] + lnb[c+1];
          *(float2*)&C[(long)r*N + c] = o;
        }
      }
    }
  } else {
    #pragma unroll
    for (int mf = 0; mf < 4; mf++) {
      #pragma unroll
      for (int hf = 0; hf < 2; hf++) {
        int r = bm + m_warp + mf*16 + g + hf*8;
        #pragma unroll
        for (int nf = 0; nf < 4; nf++) {
          int c = bn + n_warp + nf*8 + 2*l4;
          float vx = acc[mf][nf][hf*2+0];
          float vy = acc[mf][nf][hf*2+1];
          if (EPI == 3) {
            vx += bias[c+0]; vy += bias[c+1];
            vx = 0.5f*vx*(1.f + erff(vx*0.70710678118f));
            vy = 0.5f*vy*(1.f + erff(vy*0.70710678118f));
          }
          if (SPLIT) {
            int b = r / TLEN, t = r % TLEN;
            int hd = c >> 5, dh = c & 31;
            *(float2*)&C[(((long)b*NHEADS + hd)*TLEN + t)*DHEAD + dh] = make_float2(vx, vy);
          } else {
            *(float2*)&C[(long)r*N + c] = make_float2(vx, vy);
          }
        }
      }
    }
  }
}

// ---------------- Wo GEMM with fused cross-hash combine ----------------
__global__ void __launch_bounds__(256, 2) gemm_wo_fused(
    const float* __restrict__ B,
    const float* __restrict__ bias, const float* __restrict__ R,
    const float* __restrict__ lng, const float* __restrict__ lnb,
    float* __restrict__ C, int M, int N, int K) {
  __shared__ uint32_t As[2][128][AS_STRIDE];
  __shared__ uint32_t Bs[2][16][BS_STRIDE];
  int tid = threadIdx.x;
  int warp = tid >> 5, lane = tid & 31;
  int wm = warp >> 2, wn = warp & 3;
  int m_warp = wm * 64, n_warp = wn * 32;
  int g = lane >> 2, l4 = lane & 3;
  int bm = blockIdx.y * 128;

  int ar = tid >> 1, ac = (tid & 1) * 8;
  int bk = tid >> 5, bnn = (tid & 31) * 4;
  int arow = bm + ar;
  int bq = arow >> 12, tq = arow & (TLEN - 1);
  const float* Bp = B + (long)bk * N + bnn;

  float acc[4][4][4] = {};
  int ntiles = K >> 4;   // 8
  float4 fb0, fb1;
  fb0 = *(const float4*)(Bp);
  fb1 = *(const float4*)(Bp + 8 * (long)N);
  int buf = 0;
  for (int t = 0; t < ntiles; t++) {
    {
      int k0 = t*16 + ac;
      int head = k0 >> 5, dh = k0 & 31;
      long rowbase = (long)((bq*NHEADS + head)*NHASH)*TLEN + tq;
      const float* lsep = g_lse + rowbase;
      float l0 = lsep[0], l1 = lsep[TLEN], l2 = lsep[2*TLEN], l3 = lsep[3*TLEN];
      float mm = fmaxf(fmaxf(l0, l1), fmaxf(l2, l3));
      float w0 = exp_fast(l0 - mm), w1 = exp_fast(l1 - mm);
      float w2 = exp_fast(l2 - mm), w3 = exp_fast(l3 - mm);
      float invw = 1.f / (w0 + w1 + w2 + w3);
      w0 *= invw; w1 *= invw; w2 *= invw; w3 *= invw;
      const __half* sop = g_so16 + rowbase*DHEAD + dh;
      uint4 u0 = *(const uint4*)(sop);
      uint4 u1 = *(const uint4*)(sop + (long)TLEN*DHEAD);
      uint4 u2 = *(const uint4*)(sop + 2L*TLEN*DHEAD);
      uint4 u3 = *(const uint4*)(sop + 3L*TLEN*DHEAD);
      const __half2* p0 = (const __half2*)&u0;
      const __half2* p1 = (const __half2*)&u1;
      const __half2* p2 = (const __half2*)&u2;
      const __half2* p3 = (const __half2*)&u3;
      #pragma unroll
      for (int i = 0; i < 4; i++) {
        float2 a0 = __half22float2(p0[i]);
        float2 a1 = __half22float2(p1[i]);
        float2 a2 = __half22float2(p2[i]);
        float2 a3 = __half22float2(p3[i]);
        float vx = w0*a0.x + w1*a1.x + w2*a2.x + w3*a3.x;
        float vy = w0*a0.y + w1*a1.y + w2*a2.y + w3*a3.y;
        As[buf][ar][ac + 2*i    ] = f2tf(vx);
        As[buf][ar][ac + 2*i + 1] = f2tf(vy);
      }
    }
    Bs[buf][bk][bnn+0] = f2tf(fb0.x); Bs[buf][bk][bnn+1] = f2tf(fb0.y);
    Bs[buf][bk][bnn+2] = f2tf(fb0.z); Bs[buf][bk][bnn+3] = f2tf(fb0.w);
    Bs[buf][bk+8][bnn+0] = f2tf(fb1.x); Bs[buf][bk+8][bnn+1] = f2tf(fb1.y);
    Bs[buf][bk+8][bnn+2] = f2tf(fb1.z); Bs[buf][bk+8][bnn+3] = f2tf(fb1.w);
    __syncthreads();
    if (t + 1 < ntiles) {
      fb0 = *(const float4*)(Bp + (long)((t+1)*16) * N);
      fb1 = *(const float4*)(Bp + (long)((t+1)*16 + 8) * N);
    }
    #pragma unroll
    for (int k8 = 0; k8 < 16; k8 += 8) {
      uint32_t afr[4][4], bfr[4][2];
      #pragma unroll
      for (int mf = 0; mf < 4; mf++) {
        int mr = m_warp + mf*16 + g;
        afr[mf][0] = As[buf][mr    ][k8 + l4];
        afr[mf][1] = As[buf][mr + 8][k8 + l4];
        afr[mf][2] = As[buf][mr    ][k8 + l4 + 4];
        afr[mf][3] = As[buf][mr + 8][k8 + l4 + 4];
      }
      #pragma unroll
      for (int nf = 0; nf < 4; nf++) {
        int nc = n_warp + nf*8 + g;
        bfr[nf][0] = Bs[buf][k8 + l4    ][nc];
        bfr[nf][1] = Bs[buf][k8 + l4 + 4][nc];
      }
      #pragma unroll
      for (int mf = 0; mf < 4; mf++)
        #pragma unroll
        for (int nf = 0; nf < 4; nf++)
          mma_tf32(acc[mf][nf], afr[mf], bfr[nf]);
    }
    buf ^= 1;
  }

  float* Ssum = (float*)As;
  float* Ssq  = ((float*)As) + 512;
  __syncthreads();
  float psum[4][2], psq[4][2];
  #pragma unroll
  for (int mf = 0; mf < 4; mf++) {
    #pragma unroll
    for (int hf = 0; hf < 2; hf++) {
      int r = bm + m_warp + mf*16 + g + hf*8;
      float s = 0.f, sq = 0.f;
      #pragma unroll
      for (int nf = 0; nf < 4; nf++) {
        int c = n_warp + nf*8 + 2*l4;
        #pragma unroll
        for (int p = 0; p < 2; p++) {
          float v = acc[mf][nf][hf*2+p] + bias[c+p] + R[(long)r*N + c + p];
          acc[mf][nf][hf*2+p] = v;
          s += v; sq += v*v;
        }
      }
      s  += __shfl_xor_sync(0xffffffffu, s, 1);
      s  += __shfl_xor_sync(0xffffffffu, s, 2);
      sq += __shfl_xor_sync(0xffffffffu, sq, 1);
      sq += __shfl_xor_sync(0xffffffffu, sq, 2);
      psum[mf][hf] = s; psq[mf][hf] = sq;
    }
  }
  if (l4 == 0) {
    #pragma unroll
    for (int mf = 0; mf < 4; mf++)
      #pragma unroll
      for (int hf = 0; hf < 2; hf++) {
        int rl = m_warp + mf*16 + g + hf*8;
        Ssum[rl*4 + wn] = psum[mf][hf];
        Ssq [rl*4 + wn] = psq[mf][hf];
      }
  }
  __syncthreads();
  #pragma unroll
  for (int mf = 0; mf < 4; mf++) {
    #pragma unroll
    for (int hf = 0; hf < 2; hf++) {
      int rl = m_warp + mf*16 + g + hf*8;
      int r = bm + rl;
      float s  = Ssum[rl*4+0] + Ssum[rl*4+1] + Ssum[rl*4+2] + Ssum[rl*4+3];
      float sq = Ssq [rl*4+0] + Ssq [rl*4+1] + Ssq [rl*4+2] + Ssq [rl*4+3];
      float mean = s * (1.f/128.f);
      float var = sq * (1.f/128.f) - mean*mean;
      float rstd = rsqrtf(var + 1e-5f);
      #pragma unroll
      for (int nf = 0; nf < 4; nf++) {
        int c = n_warp + nf*8 + 2*l4;
        float2 o;
        o.x = (acc[mf][nf][hf*2+0] - mean)*rstd*lng[c+0] + lnb[c+0];
        o.y = (acc[mf][nf][hf*2+1] - mean)*rstd*lng[c+1] + lnb[c+1];
        *(float2*)&C[(long)r*N + c] = o;
      }
    }
  }
}

// ---------------- fused rotation + argmax ----------------
#define ROT_ROWS 64
__global__ void __launch_bounds__(128) rot_argmax_kernel(const float* __restrict__ rot_l) {
  __shared__ __align__(16) float qT[32][ROT_ROWS + 4];
  int tid = threadIdx.x, lane = tid & 31, h = tid >> 5;
  long row0 = (long)blockIdx.x * ROT_ROWS;
  int bh = (int)(row0 >> 12);
  int t0 = (int)(row0 & (TLEN - 1));

  float rcol[32];
  #pragma unroll
  for (int d = 0; d < 32; d++) rcol[d] = rot_l[d*128 + tid];

  {
    int r = tid >> 1;
    int half = (tid & 1) * 16;
    const float* gq = g_qk + (row0 + r)*DHEAD + half;
    #pragma unroll
    for (int f = 0; f < 4; f++) {
      float4 v = *(const float4*)(gq + f*4);
      qT[half + f*4 + 0][r] = v.x; qT[half + f*4 + 1][r] = v.y;
      qT[half + f*4 + 2][r] = v.z; qT[half + f*4 + 3][r] = v.w;
    }
  }
  __syncthreads();

  unsigned char* bp = g_bkt + (bh*NHASH + h)*TLEN + t0;
  #pragma unroll 4
  for (int rg = 0; rg < ROT_ROWS/4; rg++) {
    float a0 = 0.f, a1 = 0.f, a2 = 0.f, a3 = 0.f;
    #pragma unroll
    for (int d = 0; d < 32; d++) {
      float4 q4 = *(const float4*)&qT[d][rg*4];
      float r = rcol[d];
      a0 += q4.x * r; a1 += q4.y * r; a2 += q4.z * r; a3 += q4.w * r;
    }
    #pragma unroll
    for (int rr = 0; rr < 4; rr++) {
      float v = (rr == 0) ? a0 : (rr == 1) ? a1 : (rr == 2) ? a2 : a3;
      uint32_t key = __float_as_uint(fabsf(v));
      uint32_t mx = __reduce_max_sync(0xffffffffu, key);
      bool eq = (key == mx);
      bool pos = (v >= -v);
      unsigned bpos = __ballot_sync(0xffffffffu, eq && pos);
      unsigned bneg = __ballot_sync(0xffffffffu, eq && !pos);
      int bucket = bpos ? (__ffs(bpos) - 1) : (__ffs(bneg) + 31);
      if (lane == 0) bp[rg*4 + rr] = (unsigned char)bucket;
    }
  }
}

// ---------------- counting sort: histogram + scan ----------------
__global__ void hist_kernel() {
  __shared__ int cnt[256];
  int bh = blockIdx.x, tid = threadIdx.x;
  cnt[tid] = 0; __syncthreads();
  const unsigned char* bp = g_bkt + bh*ITEMS;
  for (int i = tid; i < ITEMS; i += 256) {
    int gb = ((i >> 12) << 6) + bp[i];
    atomicAdd(&cnt[gb], 1);
  }
  __syncthreads();
  if (tid == 0) {
    int s = 0;
    #pragma unroll 8
    for (int j = 0; j < 256; j++) { g_base[bh*256 + j] = s; s += cnt[j]; }
  }
}

__global__ void __launch_bounds__(1024) place_kernel() {
  int bhh = blockIdx.x;
  int bh = bhh >> 2, h = bhh & 3;
  int warp = threadIdx.x >> 5, lane = threadIdx.x & 31;
  const unsigned char* bp = g_bkt + (bh*NHASH + h)*TLEN;
  #pragma unroll
  for (int s = 0; s < 2; s++) {
    int lb = warp*2 + s;
    int base = g_base[bh*256 + h*64 + lb];
    for (int t0 = 0; t0 < TLEN; t0 += 32) {
      int my = bp[t0 + lane];
      unsigned mask = __ballot_sync(0xffffffffu, my == lb);
      if (my == lb) {
        int p = base + __popc(mask & ((1u << lane) - 1u));
        g_st[bh*ITEMS + p] = t0 + lane;
      }
      base += __popc(mask);
    }
  }
}

// ---------------- tensor-core LSH attention: 2 chunks / CTA, full fp16 ----------------
// 256 threads, 8 warps. group 0 -> chunk c0 (keys [0,128)), group 1 -> c1 (keys [64,192)).
// smem (words): region A @0 = max( qS16 half[128][40] (2560w) + kS16 half[192][40] (3840w) = 6400w,
//                                  pS16 half[128][136] = 8704w (aliases after dots) ) = 8704
//               vS16 half[32][200] @8704 (3200w) | sKt[192] @11904  -> total 12096
#define ATTN_SMEM_WORDS 12096
__global__ void __launch_bounds__(256, 2) attn_kernel() {
  extern __shared__ __align__(16) uint32_t smw[];
  __half*   qS16 = (__half*)smw;              // [128][40] raw Q
  uint32_t* qW   = smw;                       // stride 20 w/row
  __half*   kS16 = (__half*)(smw + 2560);     // [192][40] normalized K
  uint32_t* kW   = smw + 2560;                // stride 20 w/row
  __half*   pS16 = (__half*)smw;              // [128][136] aliases region A
  uint32_t* pW   = smw;                       // stride 68 w/row
  __half*   vS16 = (__half*)(smw + 8704);     // [32][200]
  uint32_t* vW   = smw + 8704;                // stride 100 w/row
  int* sKt = (int*)(smw + 11904);             // [192]

  int bh = blockIdx.x >> 7;
  int cp = blockIdx.x & 127;
  int c0 = cp * 2;
  int hh = c0 >> 6;
  int tid = threadIdx.x;
  int lane = tid & 31, warp = tid >> 5;
  int group = warp >> 2, wg = warp & 3;
  int g = lane >> 2, l4 = lane & 3;

  if (tid < 192) {
    int p = (c0*64 + tid + ITEMS - 64) & (ITEMS - 1);
    sKt[tid] = g_st[bh*ITEMS + p];
  }
  __syncthreads();

  if (tid < 192) {
    int j = tid;
    int t = sKt[j];
    const float* gk = g_qk + ((long)bh*TLEN + t)*DHEAD;
    const float* gv = g_v  + ((long)bh*TLEN + t)*DHEAD;
    float4 kr[8];
    float ss = 0.f;
    #pragma unroll
    for (int f = 0; f < 8; f++) {
      kr[f] = *(const float4*)(gk + f*4);
      ss += kr[f].x*kr[f].x + kr[f].y*kr[f].y + kr[f].z*kr[f].z + kr[f].w*kr[f].w;
    }
    if (j >= 64) {                 // raw Q row
      int qr = j - 64;
      #pragma unroll
      for (int f = 0; f < 8; f++) {
        *(__half2*)&qS16[qr*40 + f*4    ] = __floats2half2_rn(kr[f].x, kr[f].y);
        *(__half2*)&qS16[qr*40 + f*4 + 2] = __floats2half2_rn(kr[f].z, kr[f].w);
      }
    }
    float inv = ATTN_SCALE / fmaxf(sqrtf(ss), 1e-12f);
    #pragma unroll
    for (int f = 0; f < 8; f++) {
      *(__half2*)&kS16[j*40 + f*4    ] = __floats2half2_rn(kr[f].x * inv, kr[f].y * inv);
      *(__half2*)&kS16[j*40 + f*4 + 2] = __floats2half2_rn(kr[f].z * inv, kr[f].w * inv);
    }
    #pragma unroll
    for (int f = 0; f < 8; f++) {
      float4 vv = *(const float4*)(gv + f*4);
      vS16[(f*4+0)*200 + j] = __float2half_rn(vv.x);
      vS16[(f*4+1)*200 + j] = __float2half_rn(vv.y);
      vS16[(f*4+2)*200 + j] = __float2half_rn(vv.z);
      vS16[(f*4+3)*200 + j] = __float2half_rn(vv.w);
    }
  }
  __syncthreads();

  // ---- dots: S = Q*K^T (fp16, m16n8k16), over this group's 128-key window ----
  int qbase = group*64 + wg*16;
  int joff  = group*64;
  float s[16][4];
  #pragma unroll
  for (int nt = 0; nt < 16; nt++)
    #pragma unroll
    for (int p = 0; p < 4; p++) s[nt][p] = 0.f;
  int r0 = qbase + g, r1 = qbase + g + 8;
  #pragma unroll
  for (int k16 = 0; k16 < 32; k16 += 16) {
    uint32_t a0 = qW[r0*20 + k16/2 + l4];
    uint32_t a1 = qW[r1*20 + k16/2 + l4];
    uint32_t a2 = qW[r0*20 + k16/2 + 4 + l4];
    uint32_t a3 = qW[r1*20 + k16/2 + 4 + l4];
    #pragma unroll
    for (int nt = 0; nt < 16; nt++) {
      int n = joff + nt*8 + g;
      uint32_t b0 = kW[n*20 + k16/2 + l4];
      uint32_t b1 = kW[n*20 + k16/2 + 4 + l4];
      mma_f16(s[nt], a0, a1, a2, a3, b0, b1);
    }
  }
  __syncthreads();   // ALL warps done reading qS/kS -> pS16 may alias

  // ---- self-mask + softmax; write P (fp16, per-warp rows only) ----
  int qt0 = sKt[64 + r0], qt1 = sKt[64 + r1];
  float m0 = -1e30f, m1 = -1e30f;
  #pragma unroll
  for (int nt = 0; nt < 16; nt++) {
    int j0 = nt*8 + 2*l4;
    int kt0 = sKt[joff + j0], kt1 = sKt[joff + j0 + 1];
    if (kt0 == qt0) s[nt][0] = -5e4f;
    if (kt1 == qt0) s[nt][1] = -5e4f;
    if (kt0 == qt1) s[nt][2] = -5e4f;
    if (kt1 == qt1) s[nt][3] = -5e4f;
    m0 = fmaxf(m0, fmaxf(s[nt][0], s[nt][1]));
    m1 = fmaxf(m1, fmaxf(s[nt][2], s[nt][3]));
  }
  m0 = fmaxf(m0, __shfl_xor_sync(0xffffffffu, m0, 1));
  m0 = fmaxf(m0, __shfl_xor_sync(0xffffffffu, m0, 2));
  m1 = fmaxf(m1, __shfl_xor_sync(0xffffffffu, m1, 1));
  m1 = fmaxf(m1, __shfl_xor_sync(0xffffffffu, m1, 2));
  float sum0 = 0.f, sum1 = 0.f;
  #pragma unroll
  for (int nt = 0; nt < 16; nt++) {
    int j0 = nt*8 + 2*l4;
    __half h00 = __float2half_rn(exp_fast(s[nt][0] - m0));
    __half h01 = __float2half_rn(exp_fast(s[nt][1] - m0));
    __half h10 = __float2half_rn(exp_fast(s[nt][2] - m1));
    __half h11 = __float2half_rn(exp_fast(s[nt][3] - m1));
    sum0 += __half2float(h00) + __half2float(h01);
    sum1 += __half2float(h10) + __half2float(h11);
    __half2 v0; v0.x = h00; v0.y = h01;
    __half2 v1; v1.x = h10; v1.y = h11;
    *(__half2*)&pS16[r0*136 + j0] = v0;
    *(__half2*)&pS16[r1*136 + j0] = v1;
  }
  sum0 += __shfl_xor_sync(0xffffffffu, sum0, 1);
  sum0 += __shfl_xor_sync(0xffffffffu, sum0, 2);
  sum1 += __shfl_xor_sync(0xffffffffu, sum1, 1);
  sum1 += __shfl_xor_sync(0xffffffffu, sum1, 2);
  long lbase = (long)(bh*NHASH + hh)*TLEN;
  if (l4 == 0) {
    g_lse[lbase + qt0] = m0 + __logf(sum0);
    g_lse[lbase + qt1] = m1 + __logf(sum1);
  }
  __syncwarp();     // pS16 rows are per-warp

  // ---- PV: O = P*V, fp16 mma m16n8k16, k over this group's 128 keys ----
  float o[4][4];
  #pragma unroll
  for (int nt = 0; nt < 4; nt++)
    #pragma unroll
    for (int p = 0; p < 4; p++) o[nt][p] = 0.f;
  #pragma unroll
  for (int k16 = 0; k16 < 128; k16 += 16) {
    uint32_t a0 = pW[r0*68 + k16/2 + l4];
    uint32_t a1 = pW[r1*68 + k16/2 + l4];
    uint32_t a2 = pW[r0*68 + k16/2 + 4 + l4];
    uint32_t a3 = pW[r1*68 + k16/2 + 4 + l4];
    #pragma unroll
    for (int nt = 0; nt < 4; nt++) {
      uint32_t b0 = vW[(nt*8 + g)*100 + (joff + k16)/2 + l4];
      uint32_t b1 = vW[(nt*8 + g)*100 + (joff + k16)/2 + 4 + l4];
      mma_f16(o[nt], a0, a1, a2, a3, b0, b1);
    }
  }
  float inv0 = 1.f / sum0, inv1 = 1.f / sum1;
  __half* outp = g_so16 + lbase*DHEAD;
  #pragma unroll
  for (int nt = 0; nt < 4; nt++) {
    int d0 = nt*8 + 2*l4;
    *(__half2*)&outp[(long)qt0*DHEAD + d0] = __floats2half2_rn(o[nt][0]*inv0, o[nt][1]*inv0);
    *(__half2*)&outp[(long)qt1*DHEAD + d0] = __floats2half2_rn(o[nt][2]*inv1, o[nt][3]*inv1);
  }
}

// ---------------- final layernorm, tail rows only ----------------
__global__ void ln_tail_kernel(const float* __restrict__ in, float* __restrict__ out,
                               const float* __restrict__ g, const float* __restrict__ bb) {
  int idx = blockIdx.x;
  int b = idx >> 10, tt = idx & (PRED - 1);
  long row = (long)b*TLEN + SENC + tt;
  int d = threadIdx.x;
  __shared__ float red[4];
  float x = in[row*DMODEL + d];
  float s = x;
  #pragma unroll
  for (int off = 16; off; off >>= 1) s += __shfl_xor_sync(0xffffffffu, s, off);
  if ((d & 31) == 0) red[d >> 5] = s;
  __syncthreads();
  float mean = (red[0]+red[1]+red[2]+red[3]) * (1.f/DMODEL);
  float dv = x - mean;
  float s2 = dv*dv;
  #pragma unroll
  for (int off = 16; off; off >>= 1) s2 += __shfl_xor_sync(0xffffffffu, s2, off);
  __syncthreads();
  if ((d & 31) == 0) red[d >> 5] = s2;
  __syncthreads();
  float var = (red[0]+red[1]+red[2]+red[3]) * (1.f/DMODEL);
  out[row*DMODEL + d] = dv * rsqrtf(var + 1e-5f) * g[d] + bb[d];
}

// ---------------- head: parallel partial logits ----------------
__global__ void head_part_kernel(const float* __restrict__ projw, const float* __restrict__ projb,
                                 const float* __restrict__ fcw) {
  int b = blockIdx.x, chunk = blockIdx.y;
  int tid = threadIdx.x;
  int tt = chunk * 64 + tid;
  const float* hh = g_res + ((long)b*TLEN + SENC + tt)*DMODEL;
  float o4[4];
  #pragma unroll
  for (int cc = 0; cc < 4; cc++) {
    float a = projb[cc];
    #pragma unroll 8
    for (int d = 0; d < DMODEL; d++) a += hh[d]*projw[d*4 + cc];
    o4[cc] = a;
  }
  float lg0 = 0.f, lg1 = 0.f, lg2 = 0.f;
  #pragma unroll
  for (int cc = 0; cc < 4; cc++) {
    int idx = (tt*4 + cc)*3;
    lg0 += o4[cc]*fcw[idx+0];
    lg1 += o4[cc]*fcw[idx+1];
    lg2 += o4[cc]*fcw[idx+2];
  }
  __shared__ float red[3][64];
  red[0][tid] = lg0; red[1][tid] = lg1; red[2][tid] = lg2;
  __syncthreads();
  for (int off = 32; off; off >>= 1) {
    if (tid < off) {
      red[0][tid] += red[0][tid+off];
      red[1][tid] += red[1][tid+off];
      red[2][tid] += red[2][tid+off];
    }
    __syncthreads();
  }
  if (tid == 0) {
    g_part[(b*HCHUNKS + chunk)*3 + 0] = red[0][0];
    g_part[(b*HCHUNKS + chunk)*3 + 1] = red[1][0];
    g_part[(b*HCHUNKS + chunk)*3 + 2] = red[2][0];
  }
}

__global__ void head_finish_kernel(const float* __restrict__ fcb, float* __restrict__ dout) {
  int b = threadIdx.x;
  if (b >= BSZ) return;
  float l0 = fcb[0], l1 = fcb[1], l2 = fcb[2];
  for (int c = 0; c < HCHUNKS; c++) {
    l0 += g_part[(b*HCHUNKS + c)*3 + 0];
    l1 += g_part[(b*HCHUNKS + c)*3 + 1];
    l2 += g_part[(b*HCHUNKS + c)*3 + 2];
  }
  float mx = fmaxf(l0, fmaxf(l1, l2));
  float e0 = expf(l0-mx), e1 = expf(l1-mx), e2 = expf(l2-mx);
  float is = 1.f/(e0+e1+e2);
  dout[b*3+0] = e0*is; dout[b*3+1] = e1*is; dout[b*3+2] = e2*is;
}

// ---------------- host launch ----------------
extern "C" void kernel_launch(void* const* d_in, const int* in_sizes, int n_in,
                              void* d_out, int out_size) {
  const float* x_enc      = (const float*)d_in[0];
  const float* x_mark_enc = (const float*)d_in[1];
  const float* x_dec      = (const float*)d_in[2];
  const float* x_mark_dec = (const float*)d_in[3];
  const float* conv_w     = (const float*)d_in[4];
  const float* timef_w    = (const float*)d_in[5];
  const float* Wqk        = (const float*)d_in[6];
  const float* Wv         = (const float*)d_in[7];
  const float* Wo         = (const float*)d_in[8];
  const float* bo         = (const float*)d_in[9];
  const float* rot        = (const float*)d_in[10];
  const float* ln1_g      = (const float*)d_in[11];
  const float* ln1_b      = (const float*)d_in[12];
  const float* ln2_g      = (const float*)d_in[13];
  const float* ln2_b      = (const float*)d_in[14];
  const float* w1         = (const float*)d_in[15];
  const float* b1         = (const float*)d_in[16];
  const float* w2         = (const float*)d_in[17];
  const float* b2         = (const float*)d_in[18];
  const float* lnf_g      = (const float*)d_in[19];
  const float* lnf_b      = (const float*)d_in[20];
  const float* proj_w     = (const float*)d_in[21];
  const float* proj_b     = (const float*)d_in[22];
  const float* fc1_w      = (const float*)d_in[23];
  const float* fc1_b      = (const float*)d_in[24];
  (void)in_sizes; (void)n_in; (void)out_size;

  void* p;
  cudaGetSymbolAddress(&p, g_h);    float* ph    = (float*)p;
  cudaGetSymbolAddress(&p, g_res);  float* pres  = (float*)p;
  cudaGetSymbolAddress(&p, g_ff);   float* pff   = (float*)p;
  cudaGetSymbolAddress(&p, g_qk);   float* pqk   = (float*)p;
  cudaGetSymbolAddress(&p, g_v);    float* pv    = (float*)p;

  const int attn_smem = ATTN_SMEM_WORDS * 4;
  cudaFuncSetAttribute(attn_kernel, cudaFuncAttributeMaxDynamicSharedMemorySize, attn_smem);
  const int qk_smem = QK_SMEM_WORDS * 4;
  cudaFuncSetAttribute(gemm_qk_tf32x3, cudaFuncAttributeMaxDynamicSharedMemorySize, qk_smem);

  embed_kernel<<<MROWS, 128>>>(x_enc, x_mark_enc, x_dec, x_mark_dec, conv_w, timef_w);

  for (int l = 0; l < NLAYERS; l++) {
    const float* Wqk_l = Wqk + (long)l*DMODEL*DMODEL;
    const float* Wv_l  = Wv  + (long)l*DMODEL*DMODEL;
    const float* Wo_l  = Wo  + (long)l*DMODEL*DMODEL;
    const float* bo_l  = bo  + l*DMODEL;
    const float* rot_l = rot + (long)l*DHEAD*NHASH*(NBUCK/2);
    const float* w1_l  = w1 + (long)l*DMODEL*DFF;
    const float* b1_l  = b1 + l*DFF;
    const float* w2_l  = w2 + (long)l*DFF*DMODEL;
    const float* b2_l  = b2 + l*DMODEL;

    gemm_qk_tf32x3<<<dim3(1,256), 256, qk_smem>>>(ph, Wqk_l, pqk, MROWS, DMODEL, DMODEL);
    gemm_tf32<0,1><<<dim3(1,256), 256>>>(ph, Wv_l, nullptr, nullptr, nullptr, nullptr, pv, MROWS, DMODEL, DMODEL);

    rot_argmax_kernel<<<BHN*TLEN/ROT_ROWS, 128>>>(rot_l);

    hist_kernel<<<BHN, 256>>>();
    place_kernel<<<BHN*NHASH, 1024>>>();

    attn_kernel<<<BHN*(NCHUNK/2), 256, attn_smem>>>();

    gemm_wo_fused<<<dim3(1,256), 256>>>(Wo_l, bo_l, ph, ln1_g + l*DMODEL, ln1_b + l*DMODEL,
                                        ph, MROWS, DMODEL, DMODEL);
    gemm_tf32<3,0><<<dim3(4,256), 256>>>(ph, w1_l, b1_l, nullptr, nullptr, nullptr, pff, MROWS, DFF, DMODEL);
    gemm_tf32<1,0><<<dim3(1,256), 256>>>(pff, w2_l, b2_l, ph, ln2_g + l*DMODEL, ln2_b + l*DMODEL,
                                         ph, MROWS, DMODEL, DFF);
  }

  ln_tail_kernel<<<BSZ*PRED, 128>>>(ph, pres, lnf_g, lnf_b);
  head_part_kernel<<<dim3(BSZ, HCHUNKS), 64>>>(proj_w, proj_b, fc1_w);
  head_finish_kernel<<<1, 32>>>(fc1_b, (float*)d_out);
}